// round 1
// baseline (speedup 1.0000x reference)
#include <cuda_runtime.h>
#include <math.h>

#define BN 4096
#define DN 512
#define CN 3

// ---------------- device scratch (no allocations allowed) ----------------
__device__ float        g_fn[BN * DN];        // normalized features
__device__ unsigned int g_posd2[BN];          // per-row max d2 over same-class (uint-encoded float)
__device__ unsigned int g_negd2[BN];          // per-row min d2 over diff-class
__device__ double       g_acc[10];            // 0 pos 1 neg 2 semi 3 q 4 focal 5 wnll 6 bsum 7 lik 8 kl
__device__ int          g_cnt[CN];

// ---------------- helpers ----------------
__device__ __forceinline__ double digamma_d(double x) {
    double r = 0.0;
    while (x < 6.0) { r -= 1.0 / x; x += 1.0; }
    double f = 1.0 / (x * x);
    double psi = log(x) - 0.5 / x
        - f * (1.0 / 12.0 - f * (1.0 / 120.0 - f * (1.0 / 252.0 - f * (1.0 / 240.0 - f * (1.0 / 132.0)))));
    return psi + r;
}

// ---------------- kernels ----------------
__global__ void k_init() {
    int tid = blockIdx.x * blockDim.x + threadIdx.x;
    if (tid < BN) {
        g_posd2[tid] = 0u;
        g_negd2[tid] = 0x7F7FFFFFu;  // FLT_MAX bits
    }
    if (tid < 10) g_acc[tid] = 0.0;
    if (tid < CN) g_cnt[tid] = 0;
}

// one block (128 threads) per row: normalize features
__global__ void k_norm(const float* __restrict__ f) {
    int row = blockIdx.x;
    const float4* fr = (const float4*)(f + (size_t)row * DN);
    float4 v = fr[threadIdx.x];                 // 128 * 4 = 512
    float ss = v.x * v.x + v.y * v.y + v.z * v.z + v.w * v.w;
    for (int o = 16; o; o >>= 1) ss += __shfl_xor_sync(0xffffffffu, ss, o);
    __shared__ float sred[4];
    if ((threadIdx.x & 31) == 0) sred[threadIdx.x >> 5] = ss;
    __syncthreads();
    __shared__ float sinv;
    if (threadIdx.x == 0) {
        float tot = sred[0] + sred[1] + sred[2] + sred[3];
        float n = sqrtf(tot);
        sinv = 1.0f / fmaxf(n, 1e-12f);
    }
    __syncthreads();
    float inv = sinv;
    float4 o4 = make_float4(v.x * inv, v.y * inv, v.z * inv, v.w * inv);
    ((float4*)(g_fn + (size_t)row * DN))[threadIdx.x] = o4;
}

// row-wise scalar terms: focal, weighted-CE numerator, boundary, evidential
__global__ void k_rows(const float* __restrict__ logits, const int* __restrict__ targets,
                       const float* __restrict__ alpha, const float* __restrict__ fa,
                       const float* __restrict__ cw) {
    int i = blockIdx.x * blockDim.x + threadIdx.x;  // grid covers exactly BN
    int t = targets[i];

    float l0 = logits[3 * i], l1 = logits[3 * i + 1], l2 = logits[3 * i + 2];
    float m  = fmaxf(l0, fmaxf(l1, l2));
    float e0 = expf(l0 - m), e1 = expf(l1 - m), e2 = expf(l2 - m);
    float Z  = e0 + e1 + e2;
    float lse = m + logf(Z);
    float lp0 = l0 - lse, lp1 = l1 - lse, lp2 = l2 - lse;
    float lpt = (t == 0) ? lp0 : (t == 1) ? lp1 : lp2;
    float nll = -lpt;
    float meanlp = (lp0 + lp1 + lp2) * (1.0f / 3.0f);
    float ce_ls = 0.9f * nll + 0.1f * (-meanlp);
    float pt = expf(-ce_ls);
    float om = 1.0f - pt;
    float fterm = fa[t] * om * om * ce_ls;
    float wnll  = cw[t] * nll;
    float p0 = e0 / Z, p1 = e1 / Z, p2 = e2 / Z;
    float bterm = (t == 0) ? (p1 + 0.6f * p2)
                : (t == 2) ? (p1 + 0.4f * p0)
                :            4.5f * (1.0f - p1 + 0.3f * (p0 + p2));

    // evidential (double for the special functions)
    double a0 = alpha[3 * i], a1 = alpha[3 * i + 1], a2 = alpha[3 * i + 2];
    double S  = a0 + a1 + a2 + 1e-8;
    double at = (t == 0) ? a0 : (t == 1) ? a1 : a2;
    double lik = digamma_d(S) - digamma_d(at + 1e-8);
    double b0 = (t == 0) ? 1.0 : a0;
    double b1 = (t == 1) ? 1.0 : a1;
    double b2 = (t == 2) ? 1.0 : a2;
    double ats = b0 + b1 + b2 + 1e-8;
    double dga = digamma_d(ats + 1e-8);
    double kl = lgamma(ats) - (lgamma(b0 + 1e-8) + lgamma(b1 + 1e-8) + lgamma(b2 + 1e-8))
              + (b0 - 1.0) * (digamma_d(b0 + 1e-8) - dga)
              + (b1 - 1.0) * (digamma_d(b1 + 1e-8) - dga)
              + (b2 - 1.0) * (digamma_d(b2 + 1e-8) - dga);

    // block reductions
    __shared__ double sd[256];
    double vals[5] = { (double)fterm, (double)wnll, (double)bterm, lik, kl };
    #pragma unroll
    for (int r = 0; r < 5; r++) {
        sd[threadIdx.x] = vals[r];
        __syncthreads();
        for (int s = 128; s; s >>= 1) {
            if (threadIdx.x < s) sd[threadIdx.x] += sd[threadIdx.x + s];
            __syncthreads();
        }
        if (threadIdx.x == 0) atomicAdd(&g_acc[4 + r], sd[0]);
        __syncthreads();
    }
    __shared__ int sh[CN];
    if (threadIdx.x < CN) sh[threadIdx.x] = 0;
    __syncthreads();
    atomicAdd(&sh[t], 1);
    __syncthreads();
    if (threadIdx.x < CN) atomicAdd(&g_cnt[threadIdx.x], sh[threadIdx.x]);
}

// fused Gram-matrix reductions: grid (8 j-splits, 64 i-tiles), 256 threads, 4x4 per thread
__global__ void k_gram(const int* __restrict__ targets) {
    __shared__ float As[16][68];
    __shared__ float Bs[16][68];
    __shared__ int   sti[64];
    __shared__ int   stj[64];

    int tid = threadIdx.x;
    int tx = tid & 15, ty = tid >> 4;
    int i0 = blockIdx.y * 64;
    int jbase = blockIdx.x * 512;

    if (tid < 64) sti[tid] = targets[i0 + tid];

    int lrow = tid >> 2;
    int lk4  = (tid & 3) * 4;

    float pmax[4] = {0.f, 0.f, 0.f, 0.f};
    float nmin[4] = {3.4e38f, 3.4e38f, 3.4e38f, 3.4e38f};
    float posA = 0.f, negA = 0.f, semA = 0.f, qA = 0.f;

    for (int jt = 0; jt < 8; jt++) {
        int j0 = jbase + jt * 64;
        if (tid < 64) stj[tid] = targets[j0 + tid];

        float acc[4][4];
        #pragma unroll
        for (int u = 0; u < 4; u++)
            #pragma unroll
            for (int v = 0; v < 4; v++) acc[u][v] = 0.f;

        for (int kk = 0; kk < DN; kk += 16) {
            float4 av = *(const float4*)&g_fn[(size_t)(i0 + lrow) * DN + kk + lk4];
            float4 bv = *(const float4*)&g_fn[(size_t)(j0 + lrow) * DN + kk + lk4];
            __syncthreads();
            As[lk4 + 0][lrow] = av.x; As[lk4 + 1][lrow] = av.y;
            As[lk4 + 2][lrow] = av.z; As[lk4 + 3][lrow] = av.w;
            Bs[lk4 + 0][lrow] = bv.x; Bs[lk4 + 1][lrow] = bv.y;
            Bs[lk4 + 2][lrow] = bv.z; Bs[lk4 + 3][lrow] = bv.w;
            __syncthreads();
            #pragma unroll
            for (int k = 0; k < 16; k++) {
                float4 a = *(const float4*)&As[k][ty * 4];
                float4 b = *(const float4*)&Bs[k][tx * 4];
                acc[0][0] += a.x * b.x; acc[0][1] += a.x * b.y; acc[0][2] += a.x * b.z; acc[0][3] += a.x * b.w;
                acc[1][0] += a.y * b.x; acc[1][1] += a.y * b.y; acc[1][2] += a.y * b.z; acc[1][3] += a.y * b.w;
                acc[2][0] += a.z * b.x; acc[2][1] += a.z * b.y; acc[2][2] += a.z * b.z; acc[2][3] += a.z * b.w;
                acc[3][0] += a.w * b.x; acc[3][1] += a.w * b.y; acc[3][2] += a.w * b.z; acc[3][3] += a.w * b.w;
            }
        }
        __syncthreads();

        // fused epilogue
        #pragma unroll
        for (int u = 0; u < 4; u++) {
            int gi = i0 + ty * 4 + u;
            int tiv = sti[ty * 4 + u];
            #pragma unroll
            for (int v = 0; v < 4; v++) {
                int gj = j0 + tx * 4 + v;
                int tjv = stj[tx * 4 + v];
                float s = acc[u][v];
                float oms = 1.0f - s;
                float ee = oms * oms;
                float d2 = fmaxf(2.0f - 2.0f * s, 0.0f);
                if (tiv == tjv) {
                    posA += ee;
                    if (gi < gj) qA += ee;
                    if (tiv == 1) semA += ee;
                    if (gi != gj) pmax[u] = fmaxf(pmax[u], d2);
                } else {
                    float c = fmaxf(s - 0.2f, 0.0f);
                    negA += c * c;
                    nmin[u] = fminf(nmin[u], d2);
                }
            }
        }
        __syncthreads();
    }

    // reduce per-row extrema across the 16 lanes that share the rows, then one atomic
    #pragma unroll
    for (int u = 0; u < 4; u++) {
        float pm = pmax[u], nm = nmin[u];
        for (int o = 8; o; o >>= 1) {
            pm = fmaxf(pm, __shfl_xor_sync(0xffffffffu, pm, o));
            nm = fminf(nm, __shfl_xor_sync(0xffffffffu, nm, o));
        }
        if (tx == 0) {
            int gi = i0 + ty * 4 + u;
            atomicMax(&g_posd2[gi], __float_as_uint(pm));
            atomicMin(&g_negd2[gi], __float_as_uint(nm));
        }
    }

    // reduce the four sums -> one double atomic each per block
    __shared__ float sredf[256];
    float vals[4] = {posA, negA, semA, qA};
    #pragma unroll
    for (int r = 0; r < 4; r++) {
        sredf[tid] = vals[r];
        __syncthreads();
        for (int s = 128; s; s >>= 1) {
            if (tid < s) sredf[tid] += sredf[tid + s];
            __syncthreads();
        }
        if (tid == 0) atomicAdd(&g_acc[r], (double)sredf[0]);
        __syncthreads();
    }
}

// final assembly: triplet loss from per-row extrema + combine all terms
__global__ void k_final(const int* __restrict__ targets, const float* __restrict__ cw,
                        const int* __restrict__ epoch_p, float* __restrict__ out) {
    __shared__ double sred[256];
    __shared__ int    scnt[256];
    int tid = threadIdx.x;
    int c0 = g_cnt[0], c1 = g_cnt[1], c2 = g_cnt[2];

    double tsum = 0.0; int tcnt = 0;
    for (int i = tid; i < BN; i += 256) {
        int t = targets[i];
        int ct = (t == 0) ? c0 : (t == 1) ? c1 : c2;
        bool valid = (ct >= 2) && ((BN - ct) >= 1);
        if (valid) {
            float hp = sqrtf(__uint_as_float(g_posd2[i]));
            float hn = sqrtf(__uint_as_float(g_negd2[i]));
            float margin = 1.5f * ((t == 1) ? 2.5f : 1.0f);
            float tl = fmaxf(hp - hn + margin, 0.0f);
            tsum += (double)tl;
            tcnt++;
        }
    }
    sred[tid] = tsum; scnt[tid] = tcnt;
    __syncthreads();
    for (int s = 128; s; s >>= 1) {
        if (tid < s) { sred[tid] += sred[tid + s]; scnt[tid] += scnt[tid + s]; }
        __syncthreads();
    }
    if (tid == 0) {
        double triplet = (scnt[0] > 0) ? sred[0] / (double)(scnt[0] > 1 ? scnt[0] : 1) : 0.0;
        double focal = g_acc[4] / (double)BN;
        double wsum = (double)c0 * cw[0] + (double)c1 * cw[1] + (double)c2 * cw[2];
        double ce = g_acc[5] / wsum;
        double boundary = g_acc[6] / ((double)BN + 1e-8);
        double contrastive = (g_acc[0] + g_acc[1] + 4.0 * g_acc[2]) / ((double)BN * (double)BN + 1e-8);
        long long sp = (long long)c0 * c0 + (long long)c1 * c1 + (long long)c2 * c2;
        long long npairs = (sp - BN) / 2;
        double q = g_acc[3] / (double)(npairs > 1 ? npairs : 1);
        if (c2 > 0) q *= 1.0 + 2.5 * ((double)c2 / (double)BN);
        double quality = (npairs > 0) ? q : 0.0;
        int epoch = epoch_p[0];
        double ann = (double)epoch / 25.0; ann *= ann; if (ann > 1.0) ann = 1.0;
        double evid = g_acc[7] / (double)BN + ann * 0.2 * (g_acc[8] / (double)BN);
        double total = 0.4 * focal + 0.3 * ce + 0.15 * boundary
                     + 0.1 * contrastive + 0.1 * triplet + 0.1 * quality + 0.1 * evid;
        out[0] = (float)total;
    }
}

// ---------------- launcher ----------------
extern "C" void kernel_launch(void* const* d_in, const int* in_sizes, int n_in,
                              void* d_out, int out_size) {
    const float* logits   = (const float*)d_in[0];
    const int*   targets  = (const int*)d_in[1];
    const float* features = (const float*)d_in[2];
    const float* alpha    = (const float*)d_in[3];
    const int*   epoch    = (const int*)d_in[4];
    const float* fa       = (const float*)d_in[5];
    const float* cw       = (const float*)d_in[6];
    float* out = (float*)d_out;

    k_init<<<(BN + 255) / 256, 256>>>();
    k_norm<<<BN, 128>>>(features);
    k_rows<<<BN / 256, 256>>>(logits, targets, alpha, fa, cw);
    k_gram<<<dim3(8, BN / 64), 256>>>(targets);
    k_final<<<1, 256>>>(targets, cw, epoch, out);
}

// round 2
// speedup vs baseline: 2.4050x; 2.4050x over previous
#include <cuda_runtime.h>
#include <math.h>

#define BN 4096
#define DN 512
#define CN 3
#define NT 32            // 4096 / 128 tiles per dim
#define NBLK (NT * (NT + 1) / 2)   // 528 upper-tri tile pairs

// ---------------- device scratch ----------------
__device__ float        g_fn[BN * DN];
__device__ unsigned int g_posd2[BN];
__device__ unsigned int g_negd2[BN];
__device__ double       g_acc[10];   // 0 pos 1 neg 2 semi 3 q 4 focal 5 wnll 6 bsum 7 lik 8 kl
__device__ int          g_cnt[CN];

// ---------------- helpers ----------------
__device__ __forceinline__ float digamma_f(float x) {
    float r = 0.0f;
    while (x < 6.0f) { r -= 1.0f / x; x += 1.0f; }
    float f = 1.0f / (x * x);
    return logf(x) - 0.5f / x
        - f * (1.0f/12.0f - f * (1.0f/120.0f - f * (1.0f/252.0f - f * (1.0f/240.0f))))
        + r;
}

// ---------------- kernels ----------------
__global__ void k_init() {
    int tid = blockIdx.x * blockDim.x + threadIdx.x;
    if (tid < BN) {
        g_posd2[tid] = 0u;
        g_negd2[tid] = 0x7F7FFFFFu;
    }
    if (tid < 10) g_acc[tid] = 0.0;
    if (tid < CN) g_cnt[tid] = 0;
}

__global__ void k_norm(const float* __restrict__ f) {
    int row = blockIdx.x;
    const float4* fr = (const float4*)(f + (size_t)row * DN);
    float4 v = fr[threadIdx.x];
    float ss = v.x*v.x + v.y*v.y + v.z*v.z + v.w*v.w;
    for (int o = 16; o; o >>= 1) ss += __shfl_xor_sync(0xffffffffu, ss, o);
    __shared__ float sred[4];
    if ((threadIdx.x & 31) == 0) sred[threadIdx.x >> 5] = ss;
    __syncthreads();
    __shared__ float sinv;
    if (threadIdx.x == 0) {
        float n = sqrtf(sred[0] + sred[1] + sred[2] + sred[3]);
        sinv = 1.0f / fmaxf(n, 1e-12f);
    }
    __syncthreads();
    float inv = sinv;
    ((float4*)(g_fn + (size_t)row * DN))[threadIdx.x] =
        make_float4(v.x*inv, v.y*inv, v.z*inv, v.w*inv);
}

__global__ void k_rows(const float* __restrict__ logits, const int* __restrict__ targets,
                       const float* __restrict__ alpha, const float* __restrict__ fa,
                       const float* __restrict__ cw) {
    int i = blockIdx.x * blockDim.x + threadIdx.x;
    int t = targets[i];

    float l0 = logits[3*i], l1 = logits[3*i+1], l2 = logits[3*i+2];
    float m  = fmaxf(l0, fmaxf(l1, l2));
    float e0 = expf(l0-m), e1 = expf(l1-m), e2 = expf(l2-m);
    float Z  = e0 + e1 + e2;
    float lse = m + logf(Z);
    float lp0 = l0-lse, lp1 = l1-lse, lp2 = l2-lse;
    float lpt = (t == 0) ? lp0 : (t == 1) ? lp1 : lp2;
    float nll = -lpt;
    float ce_ls = 0.9f * nll - 0.1f * ((lp0+lp1+lp2) * (1.0f/3.0f));
    float pt = expf(-ce_ls);
    float om = 1.0f - pt;
    float fterm = fa[t] * om * om * ce_ls;
    float wnll  = cw[t] * nll;
    float p0 = e0/Z, p1 = e1/Z, p2 = e2/Z;
    float bterm = (t == 0) ? (p1 + 0.6f*p2)
                : (t == 2) ? (p1 + 0.4f*p0)
                :            4.5f * (1.0f - p1 + 0.3f*(p0 + p2));

    // evidential (fp32 special functions, ~1e-6 rel accuracy)
    float a0 = alpha[3*i], a1 = alpha[3*i+1], a2 = alpha[3*i+2];
    float S  = a0 + a1 + a2 + 1e-8f;
    float at = (t == 0) ? a0 : (t == 1) ? a1 : a2;
    float lik = digamma_f(S) - digamma_f(at + 1e-8f);
    float b0 = (t == 0) ? 1.0f : a0;
    float b1 = (t == 1) ? 1.0f : a1;
    float b2 = (t == 2) ? 1.0f : a2;
    float ats = b0 + b1 + b2 + 1e-8f;
    float dga = digamma_f(ats + 1e-8f);
    float kl = lgammaf(ats) - (lgammaf(b0+1e-8f) + lgammaf(b1+1e-8f) + lgammaf(b2+1e-8f))
             + (b0-1.0f) * (digamma_f(b0+1e-8f) - dga)
             + (b1-1.0f) * (digamma_f(b1+1e-8f) - dga)
             + (b2-1.0f) * (digamma_f(b2+1e-8f) - dga);

    __shared__ double sd[256];
    double vals[5] = { (double)fterm, (double)wnll, (double)bterm, (double)lik, (double)kl };
    #pragma unroll
    for (int r = 0; r < 5; r++) {
        sd[threadIdx.x] = vals[r];
        __syncthreads();
        for (int s = 128; s; s >>= 1) {
            if (threadIdx.x < s) sd[threadIdx.x] += sd[threadIdx.x + s];
            __syncthreads();
        }
        if (threadIdx.x == 0) atomicAdd(&g_acc[4 + r], sd[0]);
        __syncthreads();
    }
    __shared__ int sh[CN];
    if (threadIdx.x < CN) sh[threadIdx.x] = 0;
    __syncthreads();
    atomicAdd(&sh[t], 1);
    __syncthreads();
    if (threadIdx.x < CN) atomicAdd(&g_cnt[threadIdx.x], sh[threadIdx.x]);
}

// symmetric fused Gram kernel: 128x128 tiles, upper triangle only, 8x8 per thread
__global__ void __launch_bounds__(256, 2) k_gram(const int* __restrict__ targets) {
    __shared__ float As[8][128];
    __shared__ float Bs[8][128];
    __shared__ int sti[128], stj[128];
    __shared__ unsigned int srp[128], srn[128], scp[128], scn[128];
    __shared__ float sredf[256];

    int tid = threadIdx.x;
    int tx = tid & 15, ty = tid >> 4;

    // decode upper-triangular tile pair (bi <= bj)
    int bi = 0, rem = blockIdx.x;
    while (rem >= NT - bi) { rem -= NT - bi; bi++; }
    int bj = bi + rem;
    int i0 = bi * 128, j0 = bj * 128;
    bool diag = (bi == bj);

    if (tid < 128) {
        sti[tid] = targets[i0 + tid];
        stj[tid] = targets[j0 + tid];
        srp[tid] = 0u;            srn[tid] = 0x7F7FFFFFu;
        scp[tid] = 0u;            scn[tid] = 0x7F7FFFFFu;
    }

    float acc[8][8];
    #pragma unroll
    for (int u = 0; u < 8; u++)
        #pragma unroll
        for (int v = 0; v < 8; v++) acc[u][v] = 0.0f;

    int lr = tid >> 1;              // row 0..127
    int lc = (tid & 1) * 4;         // k offset 0 or 4
    const float* Ap = g_fn + (size_t)(i0 + lr) * DN + lc;
    const float* Bp = g_fn + (size_t)(j0 + lr) * DN + lc;

    for (int kk = 0; kk < DN; kk += 8) {
        float4 av = *(const float4*)(Ap + kk);
        float4 bv = *(const float4*)(Bp + kk);
        __syncthreads();
        As[lc+0][lr] = av.x; As[lc+1][lr] = av.y; As[lc+2][lr] = av.z; As[lc+3][lr] = av.w;
        Bs[lc+0][lr] = bv.x; Bs[lc+1][lr] = bv.y; Bs[lc+2][lr] = bv.z; Bs[lc+3][lr] = bv.w;
        __syncthreads();
        #pragma unroll
        for (int k = 0; k < 8; k++) {
            float4 a0 = *(const float4*)&As[k][ty*8];
            float4 a1 = *(const float4*)&As[k][ty*8+4];
            float4 b0 = *(const float4*)&Bs[k][tx*8];
            float4 b1 = *(const float4*)&Bs[k][tx*8+4];
            float ar[8] = {a0.x,a0.y,a0.z,a0.w,a1.x,a1.y,a1.z,a1.w};
            float br[8] = {b0.x,b0.y,b0.z,b0.w,b1.x,b1.y,b1.z,b1.w};
            #pragma unroll
            for (int u = 0; u < 8; u++)
                #pragma unroll
                for (int v = 0; v < 8; v++)
                    acc[u][v] += ar[u] * br[v];
        }
    }
    __syncthreads();   // shared extrema arrays ready; tiles no longer needed

    // fused epilogue
    float posA = 0.f, negA = 0.f, semA = 0.f, qA = 0.f;
    float pm[8], nm[8], cm[8], cn_[8];
    #pragma unroll
    for (int u = 0; u < 8; u++) { pm[u] = 0.f; nm[u] = 3.4e38f; cm[u] = 0.f; cn_[u] = 3.4e38f; }

    #pragma unroll
    for (int u = 0; u < 8; u++) {
        int li = ty*8 + u;
        int gi = i0 + li;
        int tiv = sti[li];
        #pragma unroll
        for (int v = 0; v < 8; v++) {
            int lj = tx*8 + v;
            int gj = j0 + lj;
            float s = acc[u][v];
            float oms = 1.0f - s;
            float ee = oms * oms;
            if (diag) {
                if (gi > gj) continue;
                if (gi == gj) {
                    posA += ee;
                    if (tiv == 1) semA += ee;
                    continue;
                }
            }
            int tjv = stj[lj];
            float d2 = fmaxf(2.0f - 2.0f*s, 0.0f);
            if (tiv == tjv) {
                posA += 2.0f * ee;
                qA += ee;
                if (tiv == 1) semA += 2.0f * ee;
                pm[u] = fmaxf(pm[u], d2);
                cm[v] = fmaxf(cm[v], d2);
            } else {
                float c = fmaxf(s - 0.2f, 0.0f);
                negA += 2.0f * c * c;
                nm[u] = fminf(nm[u], d2);
                cn_[v] = fminf(cn_[v], d2);
            }
        }
    }

    // shared-memory extrema merge
    #pragma unroll
    for (int u = 0; u < 8; u++) {
        atomicMax(&srp[ty*8+u], __float_as_uint(pm[u]));
        atomicMin(&srn[ty*8+u], __float_as_uint(nm[u]));
        atomicMax(&scp[tx*8+u], __float_as_uint(cm[u]));
        atomicMin(&scn[tx*8+u], __float_as_uint(cn_[u]));
    }
    __syncthreads();
    if (tid < 128) {
        if (srp[tid] != 0u)          atomicMax(&g_posd2[i0 + tid], srp[tid]);
        if (srn[tid] != 0x7F7FFFFFu) atomicMin(&g_negd2[i0 + tid], srn[tid]);
        if (scp[tid] != 0u)          atomicMax(&g_posd2[j0 + tid], scp[tid]);
        if (scn[tid] != 0x7F7FFFFFu) atomicMin(&g_negd2[j0 + tid], scn[tid]);
    }

    // sum reductions -> double atomics
    float vals[4] = {posA, negA, semA, qA};
    #pragma unroll
    for (int r = 0; r < 4; r++) {
        sredf[tid] = vals[r];
        __syncthreads();
        for (int s = 128; s; s >>= 1) {
            if (tid < s) sredf[tid] += sredf[tid + s];
            __syncthreads();
        }
        if (tid == 0) atomicAdd(&g_acc[r], (double)sredf[0]);
        __syncthreads();
    }
}

__global__ void k_final(const int* __restrict__ targets, const float* __restrict__ cw,
                        const int* __restrict__ epoch_p, float* __restrict__ out) {
    __shared__ double sred[256];
    __shared__ int    scnt[256];
    int tid = threadIdx.x;
    int c0 = g_cnt[0], c1 = g_cnt[1], c2 = g_cnt[2];

    double tsum = 0.0; int tcnt = 0;
    for (int i = tid; i < BN; i += 256) {
        int t = targets[i];
        int ct = (t == 0) ? c0 : (t == 1) ? c1 : c2;
        if ((ct >= 2) && ((BN - ct) >= 1)) {
            float hp = sqrtf(__uint_as_float(g_posd2[i]));
            float hn = sqrtf(__uint_as_float(g_negd2[i]));
            float margin = 1.5f * ((t == 1) ? 2.5f : 1.0f);
            float tl = fmaxf(hp - hn + margin, 0.0f);
            tsum += (double)tl;
            tcnt++;
        }
    }
    sred[tid] = tsum; scnt[tid] = tcnt;
    __syncthreads();
    for (int s = 128; s; s >>= 1) {
        if (tid < s) { sred[tid] += sred[tid + s]; scnt[tid] += scnt[tid + s]; }
        __syncthreads();
    }
    if (tid == 0) {
        double triplet = (scnt[0] > 0) ? sred[0] / (double)(scnt[0] > 1 ? scnt[0] : 1) : 0.0;
        double focal = g_acc[4] / (double)BN;
        double wsum = (double)c0*cw[0] + (double)c1*cw[1] + (double)c2*cw[2];
        double ce = g_acc[5] / wsum;
        double boundary = g_acc[6] / ((double)BN + 1e-8);
        double contrastive = (g_acc[0] + g_acc[1] + 4.0*g_acc[2]) / ((double)BN*(double)BN + 1e-8);
        long long sp = (long long)c0*c0 + (long long)c1*c1 + (long long)c2*c2;
        long long npairs = (sp - BN) / 2;
        double q = g_acc[3] / (double)(npairs > 1 ? npairs : 1);
        if (c2 > 0) q *= 1.0 + 2.5 * ((double)c2 / (double)BN);
        double quality = (npairs > 0) ? q : 0.0;
        int epoch = epoch_p[0];
        double ann = (double)epoch / 25.0; ann *= ann; if (ann > 1.0) ann = 1.0;
        double evid = g_acc[7] / (double)BN + ann * 0.2 * (g_acc[8] / (double)BN);
        out[0] = (float)(0.4*focal + 0.3*ce + 0.15*boundary
                       + 0.1*contrastive + 0.1*triplet + 0.1*quality + 0.1*evid);
    }
}

// ---------------- launcher ----------------
extern "C" void kernel_launch(void* const* d_in, const int* in_sizes, int n_in,
                              void* d_out, int out_size) {
    const float* logits   = (const float*)d_in[0];
    const int*   targets  = (const int*)d_in[1];
    const float* features = (const float*)d_in[2];
    const float* alpha    = (const float*)d_in[3];
    const int*   epoch    = (const int*)d_in[4];
    const float* fa       = (const float*)d_in[5];
    const float* cw       = (const float*)d_in[6];
    float* out = (float*)d_out;

    k_init<<<(BN + 255) / 256, 256>>>();
    k_norm<<<BN, 128>>>(features);
    k_rows<<<BN / 256, 256>>>(logits, targets, alpha, fa, cw);
    k_gram<<<NBLK, 256>>>(targets);
    k_final<<<1, 256>>>(targets, cw, epoch, out);
}

// round 4
// speedup vs baseline: 5.2545x; 2.1849x over previous
#include <cuda_runtime.h>
#include <cuda_bf16.h>
#include <math.h>
#include <stdint.h>

#define BN 4096
#define DN 512
#define CN 3
#define NT 32                       // 4096/128 tiles per dim
#define NBLK (NT * (NT + 1) / 2)    // 528 upper-tri tile pairs
#define KC 64                       // K elements per chunk (bf16)
#define NCHUNK (DN / KC)            // 8
#define STAGE_BYTES 65536           // 4 tiles x 16KB
#define DSMEM_BYTES (2 * STAGE_BYTES)

// ---------------- device scratch ----------------
__device__ __align__(16) __nv_bfloat16 g_hi[BN * DN];
__device__ __align__(16) __nv_bfloat16 g_lo[BN * DN];
__device__ unsigned int g_posd2[BN];
__device__ unsigned int g_negd2[BN];
__device__ double       g_acc[10];   // 0 pos 1 neg 2 semi 3 q 4 focal 5 wnll 6 bsum 7 lik 8 kl
__device__ int          g_cnt[CN];

// ---------------- PTX helpers (base sm_103-legal only) ----------------
__device__ __forceinline__ uint32_t smem_u32(const void* p) {
    uint32_t a;
    asm("{ .reg .u64 t; cvta.to.shared.u64 t, %1; cvt.u32.u64 %0, t; }" : "=r"(a) : "l"(p));
    return a;
}
#define SW128(x) ((x) ^ (((x) >> 3) & 0x70))

__device__ __forceinline__ void cp16(uint32_t smem, const void* g) {
    asm volatile("cp.async.cg.shared.global [%0], [%1], 16;" :: "r"(smem), "l"(g));
}
#define CP_COMMIT()  asm volatile("cp.async.commit_group;" ::: "memory")
#define CP_WAIT(n)   asm volatile("cp.async.wait_group %0;" :: "n"(n) : "memory")

__device__ __forceinline__ void ldsm_x4(uint32_t& r0, uint32_t& r1, uint32_t& r2, uint32_t& r3,
                                        uint32_t addr) {
    asm volatile("ldmatrix.sync.aligned.m8n8.x4.shared.b16 {%0,%1,%2,%3}, [%4];"
                 : "=r"(r0), "=r"(r1), "=r"(r2), "=r"(r3) : "r"(addr));
}

__device__ __forceinline__ void mma_bf16(float* c, const uint32_t* a, const uint32_t* b) {
    asm volatile("mma.sync.aligned.m16n8k16.row.col.f32.bf16.bf16.f32 "
                 "{%0,%1,%2,%3}, {%4,%5,%6,%7}, {%8,%9}, {%0,%1,%2,%3};"
                 : "+f"(c[0]), "+f"(c[1]), "+f"(c[2]), "+f"(c[3])
                 : "r"(a[0]), "r"(a[1]), "r"(a[2]), "r"(a[3]), "r"(b[0]), "r"(b[1]));
}

// ---------------- misc helpers ----------------
__device__ __forceinline__ float digamma_f(float x) {
    float r = 0.0f;
    while (x < 6.0f) { r -= 1.0f / x; x += 1.0f; }
    float f = 1.0f / (x * x);
    return logf(x) - 0.5f / x
        - f * (1.0f/12.0f - f * (1.0f/120.0f - f * (1.0f/252.0f - f * (1.0f/240.0f))))
        + r;
}

// ---------------- kernels ----------------
__global__ void k_norm(const float* __restrict__ f) {
    int row = blockIdx.x;
    float4 v = ((const float4*)(f + (size_t)row * DN))[threadIdx.x];
    float ss = v.x*v.x + v.y*v.y + v.z*v.z + v.w*v.w;
    for (int o = 16; o; o >>= 1) ss += __shfl_xor_sync(0xffffffffu, ss, o);
    __shared__ float sred[4];
    if ((threadIdx.x & 31) == 0) sred[threadIdx.x >> 5] = ss;
    __syncthreads();
    __shared__ float sinv;
    if (threadIdx.x == 0) {
        float n = sqrtf(sred[0] + sred[1] + sred[2] + sred[3]);
        sinv = 1.0f / fmaxf(n, 1e-12f);
    }
    __syncthreads();
    float inv = sinv;
    float x0 = v.x*inv, x1 = v.y*inv, x2 = v.z*inv, x3 = v.w*inv;
    __nv_bfloat16 h0 = __float2bfloat16(x0), h1 = __float2bfloat16(x1);
    __nv_bfloat16 h2 = __float2bfloat16(x2), h3 = __float2bfloat16(x3);
    __nv_bfloat16 l0 = __float2bfloat16(x0 - __bfloat162float(h0));
    __nv_bfloat16 l1 = __float2bfloat16(x1 - __bfloat162float(h1));
    __nv_bfloat16 l2 = __float2bfloat16(x2 - __bfloat162float(h2));
    __nv_bfloat16 l3 = __float2bfloat16(x3 - __bfloat162float(h3));
    uint2 hv, lv;
    hv.x = (uint32_t)__bfloat16_as_ushort(h0) | ((uint32_t)__bfloat16_as_ushort(h1) << 16);
    hv.y = (uint32_t)__bfloat16_as_ushort(h2) | ((uint32_t)__bfloat16_as_ushort(h3) << 16);
    lv.x = (uint32_t)__bfloat16_as_ushort(l0) | ((uint32_t)__bfloat16_as_ushort(l1) << 16);
    lv.y = (uint32_t)__bfloat16_as_ushort(l2) | ((uint32_t)__bfloat16_as_ushort(l3) << 16);
    ((uint2*)g_hi)[(size_t)row * 128 + threadIdx.x] = hv;
    ((uint2*)g_lo)[(size_t)row * 128 + threadIdx.x] = lv;

    if (threadIdx.x == 0) { g_posd2[row] = 0u; g_negd2[row] = 0x7F7FFFFFu; }
    if (row == 0) {
        if (threadIdx.x < 10) g_acc[threadIdx.x] = 0.0;
        if (threadIdx.x < CN) g_cnt[threadIdx.x] = 0;
    }
}

__global__ void k_rows(const float* __restrict__ logits, const int* __restrict__ targets,
                       const float* __restrict__ alpha, const float* __restrict__ fa,
                       const float* __restrict__ cw) {
    int i = blockIdx.x * blockDim.x + threadIdx.x;
    int t = targets[i];

    float l0 = logits[3*i], l1 = logits[3*i+1], l2 = logits[3*i+2];
    float m  = fmaxf(l0, fmaxf(l1, l2));
    float e0 = expf(l0-m), e1 = expf(l1-m), e2 = expf(l2-m);
    float Z  = e0 + e1 + e2;
    float lse = m + logf(Z);
    float lp0 = l0-lse, lp1 = l1-lse, lp2 = l2-lse;
    float lpt = (t == 0) ? lp0 : (t == 1) ? lp1 : lp2;
    float nll = -lpt;
    float ce_ls = 0.9f * nll - 0.1f * ((lp0+lp1+lp2) * (1.0f/3.0f));
    float pt = expf(-ce_ls);
    float om = 1.0f - pt;
    float fterm = fa[t] * om * om * ce_ls;
    float wnll  = cw[t] * nll;
    float p0 = e0/Z, p1 = e1/Z, p2 = e2/Z;
    float bterm = (t == 0) ? (p1 + 0.6f*p2)
                : (t == 2) ? (p1 + 0.4f*p0)
                :            4.5f * (1.0f - p1 + 0.3f*(p0 + p2));

    float a0 = alpha[3*i], a1 = alpha[3*i+1], a2 = alpha[3*i+2];
    float S  = a0 + a1 + a2 + 1e-8f;
    float at = (t == 0) ? a0 : (t == 1) ? a1 : a2;
    float lik = digamma_f(S) - digamma_f(at + 1e-8f);
    float b0 = (t == 0) ? 1.0f : a0;
    float b1 = (t == 1) ? 1.0f : a1;
    float b2 = (t == 2) ? 1.0f : a2;
    float ats = b0 + b1 + b2 + 1e-8f;
    float dga = digamma_f(ats + 1e-8f);
    float kl = lgammaf(ats) - (lgammaf(b0+1e-8f) + lgammaf(b1+1e-8f) + lgammaf(b2+1e-8f))
             + (b0-1.0f) * (digamma_f(b0+1e-8f) - dga)
             + (b1-1.0f) * (digamma_f(b1+1e-8f) - dga)
             + (b2-1.0f) * (digamma_f(b2+1e-8f) - dga);

    __shared__ double sd[256];
    double vals[5] = { (double)fterm, (double)wnll, (double)bterm, (double)lik, (double)kl };
    #pragma unroll
    for (int r = 0; r < 5; r++) {
        sd[threadIdx.x] = vals[r];
        __syncthreads();
        for (int s = 128; s; s >>= 1) {
            if (threadIdx.x < s) sd[threadIdx.x] += sd[threadIdx.x + s];
            __syncthreads();
        }
        if (threadIdx.x == 0) atomicAdd(&g_acc[4 + r], sd[0]);
        __syncthreads();
    }
    __shared__ int sh[CN];
    if (threadIdx.x < CN) sh[threadIdx.x] = 0;
    __syncthreads();
    atomicAdd(&sh[t], 1);
    __syncthreads();
    if (threadIdx.x < CN) atomicAdd(&g_cnt[threadIdx.x], sh[threadIdx.x]);
}

// gmem -> smem stage loader (cp.async), 16 x 16B per thread
__device__ __forceinline__ void load_chunk(uint32_t sb, int i0, int j0, int c, int tid) {
    const uint4* gh4 = (const uint4*)g_hi;
    const uint4* gl4 = (const uint4*)g_lo;
    #pragma unroll
    for (int p = 0; p < 4; p++) {
        int lin = p * 256 + tid;
        int r = lin >> 3, q = lin & 7;
        uint32_t so = SW128((uint32_t)(r * 128 + q * 16));
        size_t si = (size_t)(i0 + r) * 64 + c * 8 + q;
        size_t sj = (size_t)(j0 + r) * 64 + c * 8 + q;
        cp16(sb +         so, gh4 + si);
        cp16(sb + 16384 + so, gl4 + si);
        cp16(sb + 32768 + so, gh4 + sj);
        cp16(sb + 49152 + so, gl4 + sj);
    }
}

// HMMA Gram kernel: 128x128 upper-tri tile pairs, bf16-split, fused epilogue
__global__ void __launch_bounds__(256, 1) k_gram(const int* __restrict__ targets) {
    extern __shared__ __align__(1024) char dsm_raw[];
    __shared__ int sti[128], stj[128];
    __shared__ unsigned int srp[128], srn[128], scp[128], scn[128];
    __shared__ float sredf[256];

    int tid = threadIdx.x;
    int w = tid >> 5, lane = tid & 31;
    int wm = w >> 2, wn = w & 3;     // warp grid 2 x 4 -> 64x32 region per warp
    uint32_t dsm = smem_u32(dsm_raw);

    // decode upper-tri pair (bi <= bj)
    int bi = 0, rem = blockIdx.x;
    while (rem >= NT - bi) { rem -= NT - bi; bi++; }
    int bj = bi + rem;
    int i0 = bi * 128, j0 = bj * 128;
    bool diag = (bi == bj);

    if (tid < 128) {
        sti[tid] = targets[i0 + tid];
        stj[tid] = targets[j0 + tid];
        srp[tid] = 0u;            srn[tid] = 0x7F7FFFFFu;
        scp[tid] = 0u;            scn[tid] = 0x7F7FFFFFu;
    }

    float acc[4][4][4];
    #pragma unroll
    for (int am = 0; am < 4; am++)
        #pragma unroll
        for (int bn = 0; bn < 4; bn++)
            #pragma unroll
            for (int e = 0; e < 4; e++) acc[am][bn][e] = 0.0f;

    // precomputed ldmatrix offsets (geometry identical for hi/lo)
    int a_row = wm * 64 + (lane & 15);
    int a_colb = (lane >> 4) * 8;
    int b_row = wn * 32 + (lane & 7) + ((lane >> 4) << 3);
    int b_colb = ((lane >> 3) & 1) * 8;

    load_chunk(dsm, i0, j0, 0, tid);
    CP_COMMIT();

    for (int c = 0; c < NCHUNK; c++) {
        uint32_t sb = dsm + (c & 1) * STAGE_BYTES;
        if (c < NCHUNK - 1) {
            load_chunk(dsm + ((c + 1) & 1) * STAGE_BYTES, i0, j0, c + 1, tid);
            CP_COMMIT();
            CP_WAIT(1);
        } else {
            CP_WAIT(0);
        }
        __syncthreads();

        #pragma unroll
        for (int ks = 0; ks < 4; ks++) {
            int k0 = ks * 16;
            uint32_t ah[4][4], al[4][4], bh[4][2], bl[4][2];
            #pragma unroll
            for (int am = 0; am < 4; am++) {
                uint32_t off = SW128((uint32_t)((a_row + am * 16) * 128 + (k0 + a_colb) * 2));
                ldsm_x4(ah[am][0], ah[am][1], ah[am][2], ah[am][3], sb + off);
                ldsm_x4(al[am][0], al[am][1], al[am][2], al[am][3], sb + 16384 + off);
            }
            #pragma unroll
            for (int bp = 0; bp < 2; bp++) {
                uint32_t off = SW128((uint32_t)((b_row + bp * 16) * 128 + (k0 + b_colb) * 2));
                ldsm_x4(bh[bp*2][0], bh[bp*2][1], bh[bp*2+1][0], bh[bp*2+1][1], sb + 32768 + off);
                ldsm_x4(bl[bp*2][0], bl[bp*2][1], bl[bp*2+1][0], bl[bp*2+1][1], sb + 49152 + off);
            }
            #pragma unroll
            for (int am = 0; am < 4; am++)
                #pragma unroll
                for (int bn = 0; bn < 4; bn++) {
                    mma_bf16(acc[am][bn], ah[am], bh[bn]);
                    mma_bf16(acc[am][bn], ah[am], bl[bn]);
                    mma_bf16(acc[am][bn], al[am], bh[bn]);
                }
        }
        __syncthreads();
    }

    // ---- fused epilogue (registers -> reductions) ----
    float posA = 0.f, negA = 0.f, semA = 0.f, qA = 0.f;
    float pm[8], nm[8], cm[8], cnn[8];
    #pragma unroll
    for (int e = 0; e < 8; e++) { pm[e] = 0.f; nm[e] = 3.4e38f; cm[e] = 0.f; cnn[e] = 3.4e38f; }

    int r_lo = lane >> 2;
    int c_lo = (lane & 3) * 2;

    #pragma unroll
    for (int am = 0; am < 4; am++) {
        #pragma unroll
        for (int h = 0; h < 2; h++) {
            int li = wm * 64 + am * 16 + h * 8 + r_lo;
            int gi = i0 + li;
            int tiv = sti[li];
            #pragma unroll
            for (int bn = 0; bn < 4; bn++) {
                #pragma unroll
                for (int e2 = 0; e2 < 2; e2++) {
                    int lj = wn * 32 + bn * 8 + c_lo + e2;
                    int gj = j0 + lj;
                    float s = acc[am][bn][h * 2 + e2];
                    float oms = 1.0f - s;
                    float ee = oms * oms;
                    float d2 = fmaxf(2.0f - 2.0f * s, 0.0f);
                    if (diag && gi > gj) continue;
                    if (diag && gi == gj) {
                        posA += ee;
                        if (tiv == 1) semA += ee;
                        continue;
                    }
                    int tjv = stj[lj];
                    if (tiv == tjv) {
                        posA += 2.0f * ee;
                        qA += ee;
                        if (tiv == 1) semA += 2.0f * ee;
                        pm[am*2 + h] = fmaxf(pm[am*2 + h], d2);
                        cm[bn*2 + e2] = fmaxf(cm[bn*2 + e2], d2);
                    } else {
                        float cc = fmaxf(s - 0.2f, 0.0f);
                        negA += 2.0f * cc * cc;
                        nm[am*2 + h] = fminf(nm[am*2 + h], d2);
                        cnn[bn*2 + e2] = fminf(cnn[bn*2 + e2], d2);
                    }
                }
            }
        }
    }

    // shared-memory extrema merge
    #pragma unroll
    for (int am = 0; am < 4; am++)
        #pragma unroll
        for (int h = 0; h < 2; h++) {
            int li = wm * 64 + am * 16 + h * 8 + r_lo;
            if (pm[am*2+h] > 0.0f)    atomicMax(&srp[li], __float_as_uint(pm[am*2+h]));
            if (nm[am*2+h] < 3.3e38f) atomicMin(&srn[li], __float_as_uint(nm[am*2+h]));
        }
    #pragma unroll
    for (int bn = 0; bn < 4; bn++)
        #pragma unroll
        for (int e2 = 0; e2 < 2; e2++) {
            int lj = wn * 32 + bn * 8 + c_lo + e2;
            if (cm[bn*2+e2] > 0.0f)    atomicMax(&scp[lj], __float_as_uint(cm[bn*2+e2]));
            if (cnn[bn*2+e2] < 3.3e38f) atomicMin(&scn[lj], __float_as_uint(cnn[bn*2+e2]));
        }
    __syncthreads();

    if (tid < 128) {
        if (srp[tid] != 0u)          atomicMax(&g_posd2[i0 + tid], srp[tid]);
        if (srn[tid] != 0x7F7FFFFFu) atomicMin(&g_negd2[i0 + tid], srn[tid]);
        if (scp[tid] != 0u)          atomicMax(&g_posd2[j0 + tid], scp[tid]);
        if (scn[tid] != 0x7F7FFFFFu) atomicMin(&g_negd2[j0 + tid], scn[tid]);
    }

    float vals[4] = {posA, negA, semA, qA};
    #pragma unroll
    for (int r = 0; r < 4; r++) {
        sredf[tid] = vals[r];
        __syncthreads();
        for (int s = 128; s; s >>= 1) {
            if (tid < s) sredf[tid] += sredf[tid + s];
            __syncthreads();
        }
        if (tid == 0) atomicAdd(&g_acc[r], (double)sredf[0]);
        __syncthreads();
    }
}

__global__ void k_final(const int* __restrict__ targets, const float* __restrict__ cw,
                        const int* __restrict__ epoch_p, float* __restrict__ out) {
    __shared__ double sred[256];
    __shared__ int    scnt[256];
    int tid = threadIdx.x;
    int c0 = g_cnt[0], c1 = g_cnt[1], c2 = g_cnt[2];

    double tsum = 0.0; int tcnt = 0;
    for (int i = tid; i < BN; i += 256) {
        int t = targets[i];
        int ct = (t == 0) ? c0 : (t == 1) ? c1 : c2;
        if ((ct >= 2) && ((BN - ct) >= 1)) {
            float hp = sqrtf(__uint_as_float(g_posd2[i]));
            float hn = sqrtf(__uint_as_float(g_negd2[i]));
            float margin = 1.5f * ((t == 1) ? 2.5f : 1.0f);
            float tl = fmaxf(hp - hn + margin, 0.0f);
            tsum += (double)tl;
            tcnt++;
        }
    }
    sred[tid] = tsum; scnt[tid] = tcnt;
    __syncthreads();
    for (int s = 128; s; s >>= 1) {
        if (tid < s) { sred[tid] += sred[tid + s]; scnt[tid] += scnt[tid + s]; }
        __syncthreads();
    }
    if (tid == 0) {
        double triplet = (scnt[0] > 0) ? sred[0] / (double)(scnt[0] > 1 ? scnt[0] : 1) : 0.0;
        double focal = g_acc[4] / (double)BN;
        double wsum = (double)c0*cw[0] + (double)c1*cw[1] + (double)c2*cw[2];
        double ce = g_acc[5] / wsum;
        double boundary = g_acc[6] / ((double)BN + 1e-8);
        double contrastive = (g_acc[0] + g_acc[1] + 4.0*g_acc[2]) / ((double)BN*(double)BN + 1e-8);
        long long sp = (long long)c0*c0 + (long long)c1*c1 + (long long)c2*c2;
        long long npairs = (sp - BN) / 2;
        double q = g_acc[3] / (double)(npairs > 1 ? npairs : 1);
        if (c2 > 0) q *= 1.0 + 2.5 * ((double)c2 / (double)BN);
        double quality = (npairs > 0) ? q : 0.0;
        int epoch = epoch_p[0];
        double ann = (double)epoch / 25.0; ann *= ann; if (ann > 1.0) ann = 1.0;
        double evid = g_acc[7] / (double)BN + ann * 0.2 * (g_acc[8] / (double)BN);
        out[0] = (float)(0.4*focal + 0.3*ce + 0.15*boundary
                       + 0.1*contrastive + 0.1*triplet + 0.1*quality + 0.1*evid);
    }
}

// ---------------- launcher ----------------
extern "C" void kernel_launch(void* const* d_in, const int* in_sizes, int n_in,
                              void* d_out, int out_size) {
    const float* logits   = (const float*)d_in[0];
    const int*   targets  = (const int*)d_in[1];
    const float* features = (const float*)d_in[2];
    const float* alpha    = (const float*)d_in[3];
    const int*   epoch    = (const int*)d_in[4];
    const float* fa       = (const float*)d_in[5];
    const float* cw       = (const float*)d_in[6];
    float* out = (float*)d_out;

    cudaFuncSetAttribute(k_gram, cudaFuncAttributeMaxDynamicSharedMemorySize, DSMEM_BYTES);

    k_norm<<<BN, 128>>>(features);
    k_rows<<<BN / 256, 256>>>(logits, targets, alpha, fa, cw);
    k_gram<<<NBLK, 256, DSMEM_BYTES>>>(targets);
    k_final<<<1, 256>>>(targets, cw, epoch, out);
}

// round 5
// speedup vs baseline: 5.3524x; 1.0186x over previous
#include <cuda_runtime.h>
#include <cuda_bf16.h>
#include <math.h>
#include <stdint.h>

#define BN 4096
#define DN 512
#define CN 3
#define NT 32                       // 4096/128 tiles per dim
#define NBLK (NT * (NT + 1) / 2)    // 528 upper-tri tile pairs
#define NCHUNK 8                    // K chunks of 64
#define STAGE_BYTES 65536           // 4 tiles x 16KB
#define DSMEM_BYTES (2 * STAGE_BYTES)
#define NRB 32                      // row-scalar blocks (128 thr each)

// ---------------- device scratch ----------------
__device__ __align__(16) __nv_bfloat16 g_hi[BN * DN];
__device__ __align__(16) __nv_bfloat16 g_lo[BN * DN];
__device__ unsigned int g_posd2[BN];
__device__ unsigned int g_negd2[BN];
__device__ double       g_acc[4];            // 0 pos 1 neg 2 semi 3 q  (atomics, zeroed by prep)
__device__ double       g_rows_part[NRB][5]; // per-block: fterm wnll bterm lik kl (overwritten)
__device__ int          g_cnt_part[NRB][CN]; // per-block class counts (overwritten)
__device__ int          g_done;

// ---------------- PTX helpers (base sm_103-legal only) ----------------
__device__ __forceinline__ uint32_t smem_u32(const void* p) {
    uint32_t a;
    asm("{ .reg .u64 t; cvta.to.shared.u64 t, %1; cvt.u32.u64 %0, t; }" : "=r"(a) : "l"(p));
    return a;
}
#define SW128(x) ((x) ^ (((x) >> 3) & 0x70))

__device__ __forceinline__ void cp16(uint32_t smem, const void* g) {
    asm volatile("cp.async.cg.shared.global [%0], [%1], 16;" :: "r"(smem), "l"(g));
}
#define CP_COMMIT()  asm volatile("cp.async.commit_group;" ::: "memory")
#define CP_WAIT(n)   asm volatile("cp.async.wait_group %0;" :: "n"(n) : "memory")

__device__ __forceinline__ void ldsm_x4(uint32_t& r0, uint32_t& r1, uint32_t& r2, uint32_t& r3,
                                        uint32_t addr) {
    asm volatile("ldmatrix.sync.aligned.m8n8.x4.shared.b16 {%0,%1,%2,%3}, [%4];"
                 : "=r"(r0), "=r"(r1), "=r"(r2), "=r"(r3) : "r"(addr));
}

__device__ __forceinline__ void mma_bf16(float* c, const uint32_t* a, const uint32_t* b) {
    asm volatile("mma.sync.aligned.m16n8k16.row.col.f32.bf16.bf16.f32 "
                 "{%0,%1,%2,%3}, {%4,%5,%6,%7}, {%8,%9}, {%0,%1,%2,%3};"
                 : "+f"(c[0]), "+f"(c[1]), "+f"(c[2]), "+f"(c[3])
                 : "r"(a[0]), "r"(a[1]), "r"(a[2]), "r"(a[3]), "r"(b[0]), "r"(b[1]));
}

// ---------------- misc helpers ----------------
__device__ __forceinline__ float digamma_f(float x) {
    float r = 0.0f;
    while (x < 6.0f) { r -= 1.0f / x; x += 1.0f; }
    float f = 1.0f / (x * x);
    return logf(x) - 0.5f / x
        - f * (1.0f/12.0f - f * (1.0f/120.0f - f * (1.0f/252.0f - f * (1.0f/240.0f))))
        + r;
}

// ---------------- prep kernel: norm (blocks 0..BN-1) + row scalars (blocks BN..) ----------------
__global__ void k_prep(const float* __restrict__ f, const float* __restrict__ logits,
                       const int* __restrict__ targets, const float* __restrict__ alpha,
                       const float* __restrict__ fa, const float* __restrict__ cw) {
    int tid = threadIdx.x;
    if (blockIdx.x < BN) {
        // ---- normalize + hi/lo bf16 split ----
        int row = blockIdx.x;
        float4 v = ((const float4*)(f + (size_t)row * DN))[tid];
        float ss = v.x*v.x + v.y*v.y + v.z*v.z + v.w*v.w;
        for (int o = 16; o; o >>= 1) ss += __shfl_xor_sync(0xffffffffu, ss, o);
        __shared__ float sred[4];
        if ((tid & 31) == 0) sred[tid >> 5] = ss;
        __syncthreads();
        __shared__ float sinv;
        if (tid == 0) {
            float n = sqrtf(sred[0] + sred[1] + sred[2] + sred[3]);
            sinv = 1.0f / fmaxf(n, 1e-12f);
        }
        __syncthreads();
        float inv = sinv;
        float x0 = v.x*inv, x1 = v.y*inv, x2 = v.z*inv, x3 = v.w*inv;
        __nv_bfloat16 h0 = __float2bfloat16(x0), h1 = __float2bfloat16(x1);
        __nv_bfloat16 h2 = __float2bfloat16(x2), h3 = __float2bfloat16(x3);
        __nv_bfloat16 l0 = __float2bfloat16(x0 - __bfloat162float(h0));
        __nv_bfloat16 l1 = __float2bfloat16(x1 - __bfloat162float(h1));
        __nv_bfloat16 l2 = __float2bfloat16(x2 - __bfloat162float(h2));
        __nv_bfloat16 l3 = __float2bfloat16(x3 - __bfloat162float(h3));
        uint2 hv, lv;
        hv.x = (uint32_t)__bfloat16_as_ushort(h0) | ((uint32_t)__bfloat16_as_ushort(h1) << 16);
        hv.y = (uint32_t)__bfloat16_as_ushort(h2) | ((uint32_t)__bfloat16_as_ushort(h3) << 16);
        lv.x = (uint32_t)__bfloat16_as_ushort(l0) | ((uint32_t)__bfloat16_as_ushort(l1) << 16);
        lv.y = (uint32_t)__bfloat16_as_ushort(l2) | ((uint32_t)__bfloat16_as_ushort(l3) << 16);
        ((uint2*)g_hi)[(size_t)row * 128 + tid] = hv;
        ((uint2*)g_lo)[(size_t)row * 128 + tid] = lv;

        if (tid == 0) { g_posd2[row] = 0u; g_negd2[row] = 0x7F7FFFFFu; }
        if (row == 0) {
            if (tid < 4) g_acc[tid] = 0.0;
            if (tid == 4) g_done = 0;
        }
    } else {
        // ---- row-scalar terms: focal / weighted-CE / boundary / evidential ----
        int rb = blockIdx.x - BN;
        int i = rb * 128 + tid;
        int t = targets[i];

        float l0 = logits[3*i], l1 = logits[3*i+1], l2 = logits[3*i+2];
        float m  = fmaxf(l0, fmaxf(l1, l2));
        float e0 = expf(l0-m), e1 = expf(l1-m), e2 = expf(l2-m);
        float Z  = e0 + e1 + e2;
        float lse = m + logf(Z);
        float lp0 = l0-lse, lp1 = l1-lse, lp2 = l2-lse;
        float lpt = (t == 0) ? lp0 : (t == 1) ? lp1 : lp2;
        float nll = -lpt;
        float ce_ls = 0.9f * nll - 0.1f * ((lp0+lp1+lp2) * (1.0f/3.0f));
        float pt = expf(-ce_ls);
        float om = 1.0f - pt;
        float fterm = fa[t] * om * om * ce_ls;
        float wnll  = cw[t] * nll;
        float p0 = e0/Z, p1 = e1/Z, p2 = e2/Z;
        float bterm = (t == 0) ? (p1 + 0.6f*p2)
                    : (t == 2) ? (p1 + 0.4f*p0)
                    :            4.5f * (1.0f - p1 + 0.3f*(p0 + p2));

        float a0 = alpha[3*i], a1 = alpha[3*i+1], a2 = alpha[3*i+2];
        float S  = a0 + a1 + a2 + 1e-8f;
        float at = (t == 0) ? a0 : (t == 1) ? a1 : a2;
        float lik = digamma_f(S) - digamma_f(at + 1e-8f);
        float b0 = (t == 0) ? 1.0f : a0;
        float b1 = (t == 1) ? 1.0f : a1;
        float b2 = (t == 2) ? 1.0f : a2;
        float ats = b0 + b1 + b2 + 1e-8f;
        float dga = digamma_f(ats + 1e-8f);
        float kl = lgammaf(ats) - (lgammaf(b0+1e-8f) + lgammaf(b1+1e-8f) + lgammaf(b2+1e-8f))
                 + (b0-1.0f) * (digamma_f(b0+1e-8f) - dga)
                 + (b1-1.0f) * (digamma_f(b1+1e-8f) - dga)
                 + (b2-1.0f) * (digamma_f(b2+1e-8f) - dga);

        double vals[5] = { (double)fterm, (double)wnll, (double)bterm, (double)lik, (double)kl };
        __shared__ double swp[4][5];
        int lane = tid & 31, w = tid >> 5;
        #pragma unroll
        for (int r = 0; r < 5; r++) {
            double v = vals[r];
            for (int o = 16; o; o >>= 1) v += __shfl_xor_sync(0xffffffffu, v, o);
            if (lane == 0) swp[w][r] = v;
        }
        __shared__ int sh[CN];
        if (tid < CN) sh[tid] = 0;
        __syncthreads();
        atomicAdd(&sh[t], 1);
        __syncthreads();
        if (tid < 5)  g_rows_part[rb][tid] = swp[0][tid] + swp[1][tid] + swp[2][tid] + swp[3][tid];
        if (tid < CN) g_cnt_part[rb][tid] = sh[tid];
    }
}

// gmem -> smem stage loader (cp.async), 16 x 16B per thread
__device__ __forceinline__ void load_chunk(uint32_t sb, int i0, int j0, int c, int tid) {
    const uint4* gh4 = (const uint4*)g_hi;
    const uint4* gl4 = (const uint4*)g_lo;
    #pragma unroll
    for (int p = 0; p < 4; p++) {
        int lin = p * 256 + tid;
        int r = lin >> 3, q = lin & 7;
        uint32_t so = SW128((uint32_t)(r * 128 + q * 16));
        size_t si = (size_t)(i0 + r) * 64 + c * 8 + q;
        size_t sj = (size_t)(j0 + r) * 64 + c * 8 + q;
        cp16(sb +         so, gh4 + si);
        cp16(sb + 16384 + so, gl4 + si);
        cp16(sb + 32768 + so, gh4 + sj);
        cp16(sb + 49152 + so, gl4 + sj);
    }
}

// HMMA Gram kernel + last-block finalize
__global__ void __launch_bounds__(256, 1) k_gram(const int* __restrict__ targets,
                                                 const float* __restrict__ cw,
                                                 const int* __restrict__ epoch_p,
                                                 float* __restrict__ out) {
    extern __shared__ __align__(1024) char dsm_raw[];
    __shared__ int sti[128], stj[128];
    __shared__ unsigned int srp[128], srn[128], scp[128], scn[128];
    __shared__ float sredf[256];

    int tid = threadIdx.x;
    int w = tid >> 5, lane = tid & 31;
    int wm = w >> 2, wn = w & 3;     // warp grid 2 x 4 -> 64x32 region per warp
    uint32_t dsm = smem_u32(dsm_raw);

    // decode upper-tri pair (bi <= bj)
    int bi = 0, rem = blockIdx.x;
    while (rem >= NT - bi) { rem -= NT - bi; bi++; }
    int bj = bi + rem;
    int i0 = bi * 128, j0 = bj * 128;
    bool diag = (bi == bj);

    if (tid < 128) {
        sti[tid] = targets[i0 + tid];
        stj[tid] = targets[j0 + tid];
        srp[tid] = 0u;            srn[tid] = 0x7F7FFFFFu;
        scp[tid] = 0u;            scn[tid] = 0x7F7FFFFFu;
    }

    float acc[4][4][4];
    #pragma unroll
    for (int am = 0; am < 4; am++)
        #pragma unroll
        for (int bn = 0; bn < 4; bn++)
            #pragma unroll
            for (int e = 0; e < 4; e++) acc[am][bn][e] = 0.0f;

    int a_row = wm * 64 + (lane & 15);
    int a_colb = (lane >> 4) * 8;
    int b_row = wn * 32 + (lane & 7) + ((lane >> 4) << 3);
    int b_colb = ((lane >> 3) & 1) * 8;

    load_chunk(dsm, i0, j0, 0, tid);
    CP_COMMIT();

    for (int c = 0; c < NCHUNK; c++) {
        uint32_t sb = dsm + (c & 1) * STAGE_BYTES;
        if (c < NCHUNK - 1) {
            load_chunk(dsm + ((c + 1) & 1) * STAGE_BYTES, i0, j0, c + 1, tid);
            CP_COMMIT();
            CP_WAIT(1);
        } else {
            CP_WAIT(0);
        }
        __syncthreads();

        #pragma unroll
        for (int ks = 0; ks < 4; ks++) {
            int k0 = ks * 16;
            uint32_t ah[4][4], al[4][4], bh[4][2], bl[4][2];
            #pragma unroll
            for (int am = 0; am < 4; am++) {
                uint32_t off = SW128((uint32_t)((a_row + am * 16) * 128 + (k0 + a_colb) * 2));
                ldsm_x4(ah[am][0], ah[am][1], ah[am][2], ah[am][3], sb + off);
                ldsm_x4(al[am][0], al[am][1], al[am][2], al[am][3], sb + 16384 + off);
            }
            #pragma unroll
            for (int bp = 0; bp < 2; bp++) {
                uint32_t off = SW128((uint32_t)((b_row + bp * 16) * 128 + (k0 + b_colb) * 2));
                ldsm_x4(bh[bp*2][0], bh[bp*2][1], bh[bp*2+1][0], bh[bp*2+1][1], sb + 32768 + off);
                ldsm_x4(bl[bp*2][0], bl[bp*2][1], bl[bp*2+1][0], bl[bp*2+1][1], sb + 49152 + off);
            }
            #pragma unroll
            for (int am = 0; am < 4; am++)
                #pragma unroll
                for (int bn = 0; bn < 4; bn++) {
                    mma_bf16(acc[am][bn], ah[am], bh[bn]);
                    mma_bf16(acc[am][bn], ah[am], bl[bn]);
                    mma_bf16(acc[am][bn], al[am], bh[bn]);
                }
        }
        __syncthreads();
    }

    // ---- fused epilogue ----
    float posA = 0.f, negA = 0.f, semA = 0.f, qA = 0.f;
    float pm[8], nm[8], cm[8], cnn[8];
    #pragma unroll
    for (int e = 0; e < 8; e++) { pm[e] = 0.f; nm[e] = 3.4e38f; cm[e] = 0.f; cnn[e] = 3.4e38f; }

    int r_lo = lane >> 2;
    int c_lo = (lane & 3) * 2;

    #pragma unroll
    for (int am = 0; am < 4; am++) {
        #pragma unroll
        for (int h = 0; h < 2; h++) {
            int li = wm * 64 + am * 16 + h * 8 + r_lo;
            int gi = i0 + li;
            int tiv = sti[li];
            #pragma unroll
            for (int bn = 0; bn < 4; bn++) {
                #pragma unroll
                for (int e2 = 0; e2 < 2; e2++) {
                    int lj = wn * 32 + bn * 8 + c_lo + e2;
                    int gj = j0 + lj;
                    float s = acc[am][bn][h * 2 + e2];
                    float oms = 1.0f - s;
                    float ee = oms * oms;
                    float d2 = fmaxf(2.0f - 2.0f * s, 0.0f);
                    if (diag && gi > gj) continue;
                    if (diag && gi == gj) {
                        posA += ee;
                        if (tiv == 1) semA += ee;
                        continue;
                    }
                    int tjv = stj[lj];
                    if (tiv == tjv) {
                        posA += 2.0f * ee;
                        qA += ee;
                        if (tiv == 1) semA += 2.0f * ee;
                        pm[am*2 + h] = fmaxf(pm[am*2 + h], d2);
                        cm[bn*2 + e2] = fmaxf(cm[bn*2 + e2], d2);
                    } else {
                        float cc = fmaxf(s - 0.2f, 0.0f);
                        negA += 2.0f * cc * cc;
                        nm[am*2 + h] = fminf(nm[am*2 + h], d2);
                        cnn[bn*2 + e2] = fminf(cnn[bn*2 + e2], d2);
                    }
                }
            }
        }
    }

    #pragma unroll
    for (int am = 0; am < 4; am++)
        #pragma unroll
        for (int h = 0; h < 2; h++) {
            int li = wm * 64 + am * 16 + h * 8 + r_lo;
            if (pm[am*2+h] > 0.0f)    atomicMax(&srp[li], __float_as_uint(pm[am*2+h]));
            if (nm[am*2+h] < 3.3e38f) atomicMin(&srn[li], __float_as_uint(nm[am*2+h]));
        }
    #pragma unroll
    for (int bn = 0; bn < 4; bn++)
        #pragma unroll
        for (int e2 = 0; e2 < 2; e2++) {
            int lj = wn * 32 + bn * 8 + c_lo + e2;
            if (cm[bn*2+e2] > 0.0f)     atomicMax(&scp[lj], __float_as_uint(cm[bn*2+e2]));
            if (cnn[bn*2+e2] < 3.3e38f) atomicMin(&scn[lj], __float_as_uint(cnn[bn*2+e2]));
        }
    __syncthreads();

    if (tid < 128) {
        if (srp[tid] != 0u)          atomicMax(&g_posd2[i0 + tid], srp[tid]);
        if (srn[tid] != 0x7F7FFFFFu) atomicMin(&g_negd2[i0 + tid], srn[tid]);
        if (scp[tid] != 0u)          atomicMax(&g_posd2[j0 + tid], scp[tid]);
        if (scn[tid] != 0x7F7FFFFFu) atomicMin(&g_negd2[j0 + tid], scn[tid]);
    }

    float vals[4] = {posA, negA, semA, qA};
    #pragma unroll
    for (int r = 0; r < 4; r++) {
        sredf[tid] = vals[r];
        __syncthreads();
        for (int s = 128; s; s >>= 1) {
            if (tid < s) sredf[tid] += sredf[tid + s];
            __syncthreads();
        }
        if (tid == 0) atomicAdd(&g_acc[r], (double)sredf[0]);
        __syncthreads();
    }

    // ---- last-block finalize ----
    __threadfence();
    __shared__ int s_rank;
    if (tid == 0) s_rank = atomicAdd(&g_done, 1);
    __syncthreads();
    if (s_rank != NBLK - 1) return;

    __shared__ double s_sum[5];
    __shared__ int    s_c[CN];
    if (w == 0) {
        double p[5];
        #pragma unroll
        for (int r = 0; r < 5; r++) p[r] = g_rows_part[lane][r];
        int c[CN];
        #pragma unroll
        for (int r = 0; r < CN; r++) c[r] = g_cnt_part[lane][r];
        #pragma unroll
        for (int r = 0; r < 5; r++) {
            double v = p[r];
            for (int o = 16; o; o >>= 1) v += __shfl_xor_sync(0xffffffffu, v, o);
            if (lane == 0) s_sum[r] = v;
        }
        #pragma unroll
        for (int r = 0; r < CN; r++) {
            int v = c[r];
            for (int o = 16; o; o >>= 1) v += __shfl_xor_sync(0xffffffffu, v, o);
            if (lane == 0) s_c[r] = v;
        }
    }
    __syncthreads();
    int c0 = s_c[0], c1 = s_c[1], c2 = s_c[2];

    __shared__ double sdd[256];
    __shared__ int    sci[256];
    double tsum = 0.0; int tcnt = 0;
    for (int i = tid; i < BN; i += 256) {
        int t = targets[i];
        int ct = (t == 0) ? c0 : (t == 1) ? c1 : c2;
        if ((ct >= 2) && ((BN - ct) >= 1)) {
            float hp = sqrtf(__uint_as_float(g_posd2[i]));
            float hn = sqrtf(__uint_as_float(g_negd2[i]));
            float margin = 1.5f * ((t == 1) ? 2.5f : 1.0f);
            float tl = fmaxf(hp - hn + margin, 0.0f);
            tsum += (double)tl;
            tcnt++;
        }
    }
    sdd[tid] = tsum; sci[tid] = tcnt;
    __syncthreads();
    for (int s = 128; s; s >>= 1) {
        if (tid < s) { sdd[tid] += sdd[tid + s]; sci[tid] += sci[tid + s]; }
        __syncthreads();
    }
    if (tid == 0) {
        double triplet = (sci[0] > 0) ? sdd[0] / (double)(sci[0] > 1 ? sci[0] : 1) : 0.0;
        double focal = s_sum[0] / (double)BN;
        double wsum = (double)c0*cw[0] + (double)c1*cw[1] + (double)c2*cw[2];
        double ce = s_sum[1] / wsum;
        double boundary = s_sum[2] / ((double)BN + 1e-8);
        double contrastive = (g_acc[0] + g_acc[1] + 4.0*g_acc[2]) / ((double)BN*(double)BN + 1e-8);
        long long sp = (long long)c0*c0 + (long long)c1*c1 + (long long)c2*c2;
        long long npairs = (sp - BN) / 2;
        double q = g_acc[3] / (double)(npairs > 1 ? npairs : 1);
        if (c2 > 0) q *= 1.0 + 2.5 * ((double)c2 / (double)BN);
        double quality = (npairs > 0) ? q : 0.0;
        int epoch = epoch_p[0];
        double ann = (double)epoch / 25.0; ann *= ann; if (ann > 1.0) ann = 1.0;
        double evid = s_sum[3] / (double)BN + ann * 0.2 * (s_sum[4] / (double)BN);
        out[0] = (float)(0.4*focal + 0.3*ce + 0.15*boundary
                       + 0.1*contrastive + 0.1*triplet + 0.1*quality + 0.1*evid);
    }
}

// ---------------- launcher ----------------
extern "C" void kernel_launch(void* const* d_in, const int* in_sizes, int n_in,
                              void* d_out, int out_size) {
    const float* logits   = (const float*)d_in[0];
    const int*   targets  = (const int*)d_in[1];
    const float* features = (const float*)d_in[2];
    const float* alpha    = (const float*)d_in[3];
    const int*   epoch    = (const int*)d_in[4];
    const float* fa       = (const float*)d_in[5];
    const float* cw       = (const float*)d_in[6];
    float* out = (float*)d_out;

    cudaFuncSetAttribute(k_gram, cudaFuncAttributeMaxDynamicSharedMemorySize, DSMEM_BYTES);

    k_prep<<<BN + NRB, 128>>>(features, logits, targets, alpha, fa, cw);
    k_gram<<<NBLK, 256, DSMEM_BYTES>>>(targets, cw, epoch, out);
}

// round 6
// speedup vs baseline: 5.5521x; 1.0373x over previous
#include <cuda_runtime.h>
#include <cuda_bf16.h>
#include <math.h>
#include <stdint.h>

#define BN 4096
#define DN 512
#define CN 3
#define NT 32                       // 4096/128 tiles per dim
#define NBLK (NT * (NT + 1) / 2)    // 528 upper-tri tile pairs
#define NCHUNK 8                    // K chunks of 64
#define STAGE_BYTES 65536           // 4 tiles x 16KB
#define DSMEM_BYTES (2 * STAGE_BYTES)
#define NRB 32                      // row-scalar blocks (128 thr each)
#define GT 512                      // k_gram threads

// ---------------- device scratch ----------------
__device__ __align__(16) __nv_bfloat16 g_hi[BN * DN];
__device__ __align__(16) __nv_bfloat16 g_lo[BN * DN];
__device__ unsigned int g_posd2[BN];
__device__ unsigned int g_negd2[BN];
__device__ double       g_acc[4];            // 0 pos 1 neg 2 semi 3 q
__device__ double       g_rows_part[NRB][5];
__device__ int          g_cnt_part[NRB][CN];
__device__ int          g_done;

// ---------------- PTX helpers (base sm_103-legal only) ----------------
__device__ __forceinline__ uint32_t smem_u32(const void* p) {
    uint32_t a;
    asm("{ .reg .u64 t; cvta.to.shared.u64 t, %1; cvt.u32.u64 %0, t; }" : "=r"(a) : "l"(p));
    return a;
}
#define SW128(x) ((x) ^ (((x) >> 3) & 0x70))

__device__ __forceinline__ void cp16(uint32_t smem, const void* g) {
    asm volatile("cp.async.cg.shared.global [%0], [%1], 16;" :: "r"(smem), "l"(g));
}
#define CP_COMMIT()  asm volatile("cp.async.commit_group;" ::: "memory")
#define CP_WAIT(n)   asm volatile("cp.async.wait_group %0;" :: "n"(n) : "memory")

__device__ __forceinline__ void ldsm_x4(uint32_t& r0, uint32_t& r1, uint32_t& r2, uint32_t& r3,
                                        uint32_t addr) {
    asm volatile("ldmatrix.sync.aligned.m8n8.x4.shared.b16 {%0,%1,%2,%3}, [%4];"
                 : "=r"(r0), "=r"(r1), "=r"(r2), "=r"(r3) : "r"(addr));
}

__device__ __forceinline__ void mma_bf16(float* c, const uint32_t* a, const uint32_t* b) {
    asm volatile("mma.sync.aligned.m16n8k16.row.col.f32.bf16.bf16.f32 "
                 "{%0,%1,%2,%3}, {%4,%5,%6,%7}, {%8,%9}, {%0,%1,%2,%3};"
                 : "+f"(c[0]), "+f"(c[1]), "+f"(c[2]), "+f"(c[3])
                 : "r"(a[0]), "r"(a[1]), "r"(a[2]), "r"(a[3]), "r"(b[0]), "r"(b[1]));
}

// ---------------- misc helpers ----------------
__device__ __forceinline__ float digamma_f(float x) {
    float r = 0.0f;
    while (x < 6.0f) { r -= 1.0f / x; x += 1.0f; }
    float f = 1.0f / (x * x);
    return logf(x) - 0.5f / x
        - f * (1.0f/12.0f - f * (1.0f/120.0f - f * (1.0f/252.0f - f * (1.0f/240.0f))))
        + r;
}

// ---------------- prep kernel ----------------
__global__ void k_prep(const float* __restrict__ f, const float* __restrict__ logits,
                       const int* __restrict__ targets, const float* __restrict__ alpha,
                       const float* __restrict__ fa, const float* __restrict__ cw) {
    int tid = threadIdx.x;
    if (blockIdx.x < BN) {
        int row = blockIdx.x;
        float4 v = ((const float4*)(f + (size_t)row * DN))[tid];
        float ss = v.x*v.x + v.y*v.y + v.z*v.z + v.w*v.w;
        for (int o = 16; o; o >>= 1) ss += __shfl_xor_sync(0xffffffffu, ss, o);
        __shared__ float sred[4];
        if ((tid & 31) == 0) sred[tid >> 5] = ss;
        __syncthreads();
        __shared__ float sinv;
        if (tid == 0) {
            float n = sqrtf(sred[0] + sred[1] + sred[2] + sred[3]);
            sinv = 1.0f / fmaxf(n, 1e-12f);
        }
        __syncthreads();
        float inv = sinv;
        float x0 = v.x*inv, x1 = v.y*inv, x2 = v.z*inv, x3 = v.w*inv;
        __nv_bfloat16 h0 = __float2bfloat16(x0), h1 = __float2bfloat16(x1);
        __nv_bfloat16 h2 = __float2bfloat16(x2), h3 = __float2bfloat16(x3);
        __nv_bfloat16 l0 = __float2bfloat16(x0 - __bfloat162float(h0));
        __nv_bfloat16 l1 = __float2bfloat16(x1 - __bfloat162float(h1));
        __nv_bfloat16 l2 = __float2bfloat16(x2 - __bfloat162float(h2));
        __nv_bfloat16 l3 = __float2bfloat16(x3 - __bfloat162float(h3));
        uint2 hv, lv;
        hv.x = (uint32_t)__bfloat16_as_ushort(h0) | ((uint32_t)__bfloat16_as_ushort(h1) << 16);
        hv.y = (uint32_t)__bfloat16_as_ushort(h2) | ((uint32_t)__bfloat16_as_ushort(h3) << 16);
        lv.x = (uint32_t)__bfloat16_as_ushort(l0) | ((uint32_t)__bfloat16_as_ushort(l1) << 16);
        lv.y = (uint32_t)__bfloat16_as_ushort(l2) | ((uint32_t)__bfloat16_as_ushort(l3) << 16);
        ((uint2*)g_hi)[(size_t)row * 128 + tid] = hv;
        ((uint2*)g_lo)[(size_t)row * 128 + tid] = lv;

        if (tid == 0) { g_posd2[row] = 0u; g_negd2[row] = 0x7F7FFFFFu; }
        if (row == 0) {
            if (tid < 4) g_acc[tid] = 0.0;
            if (tid == 4) g_done = 0;
        }
    } else {
        int rb = blockIdx.x - BN;
        int i = rb * 128 + tid;
        int t = targets[i];

        float l0 = logits[3*i], l1 = logits[3*i+1], l2 = logits[3*i+2];
        float m  = fmaxf(l0, fmaxf(l1, l2));
        float e0 = expf(l0-m), e1 = expf(l1-m), e2 = expf(l2-m);
        float Z  = e0 + e1 + e2;
        float lse = m + logf(Z);
        float lp0 = l0-lse, lp1 = l1-lse, lp2 = l2-lse;
        float lpt = (t == 0) ? lp0 : (t == 1) ? lp1 : lp2;
        float nll = -lpt;
        float ce_ls = 0.9f * nll - 0.1f * ((lp0+lp1+lp2) * (1.0f/3.0f));
        float pt = expf(-ce_ls);
        float om = 1.0f - pt;
        float fterm = fa[t] * om * om * ce_ls;
        float wnll  = cw[t] * nll;
        float p0 = e0/Z, p1 = e1/Z, p2 = e2/Z;
        float bterm = (t == 0) ? (p1 + 0.6f*p2)
                    : (t == 2) ? (p1 + 0.4f*p0)
                    :            4.5f * (1.0f - p1 + 0.3f*(p0 + p2));

        float a0 = alpha[3*i], a1 = alpha[3*i+1], a2 = alpha[3*i+2];
        float S  = a0 + a1 + a2 + 1e-8f;
        float at = (t == 0) ? a0 : (t == 1) ? a1 : a2;
        float lik = digamma_f(S) - digamma_f(at + 1e-8f);
        float b0 = (t == 0) ? 1.0f : a0;
        float b1 = (t == 1) ? 1.0f : a1;
        float b2 = (t == 2) ? 1.0f : a2;
        float ats = b0 + b1 + b2 + 1e-8f;
        float dga = digamma_f(ats + 1e-8f);
        float kl = lgammaf(ats) - (lgammaf(b0+1e-8f) + lgammaf(b1+1e-8f) + lgammaf(b2+1e-8f))
                 + (b0-1.0f) * (digamma_f(b0+1e-8f) - dga)
                 + (b1-1.0f) * (digamma_f(b1+1e-8f) - dga)
                 + (b2-1.0f) * (digamma_f(b2+1e-8f) - dga);

        double vals[5] = { (double)fterm, (double)wnll, (double)bterm, (double)lik, (double)kl };
        __shared__ double swp[4][5];
        int lane = tid & 31, w = tid >> 5;
        #pragma unroll
        for (int r = 0; r < 5; r++) {
            double v = vals[r];
            for (int o = 16; o; o >>= 1) v += __shfl_xor_sync(0xffffffffu, v, o);
            if (lane == 0) swp[w][r] = v;
        }
        __shared__ int sh[CN];
        if (tid < CN) sh[tid] = 0;
        __syncthreads();
        atomicAdd(&sh[t], 1);
        __syncthreads();
        if (tid < 5)  g_rows_part[rb][tid] = swp[0][tid] + swp[1][tid] + swp[2][tid] + swp[3][tid];
        if (tid < CN) g_cnt_part[rb][tid] = sh[tid];
    }
}

// gmem -> smem stage loader (cp.async), 512 threads: 8 x 16B per thread
__device__ __forceinline__ void load_chunk(uint32_t sb, int i0, int j0, int c, int tid) {
    const uint4* gh4 = (const uint4*)g_hi;
    const uint4* gl4 = (const uint4*)g_lo;
    #pragma unroll
    for (int p = 0; p < 2; p++) {
        int lin = p * GT + tid;
        int r = lin >> 3, q = lin & 7;
        uint32_t so = SW128((uint32_t)(r * 128 + q * 16));
        size_t si = (size_t)(i0 + r) * 64 + c * 8 + q;
        size_t sj = (size_t)(j0 + r) * 64 + c * 8 + q;
        cp16(sb +         so, gh4 + si);
        cp16(sb + 16384 + so, gl4 + si);
        cp16(sb + 32768 + so, gh4 + sj);
        cp16(sb + 49152 + so, gl4 + sj);
    }
}

// HMMA Gram kernel (512 thr, warp grid 4x4, warp tile 32x32) + last-block finalize
__global__ void __launch_bounds__(GT, 1) k_gram(const int* __restrict__ targets,
                                                const float* __restrict__ cw,
                                                const int* __restrict__ epoch_p,
                                                float* __restrict__ out) {
    extern __shared__ __align__(1024) char dsm_raw[];
    __shared__ int sti[128], stj[128];
    __shared__ unsigned int srp[128], srn[128], scp[128], scn[128];
    __shared__ float sredf[GT];

    int tid = threadIdx.x;
    int w = tid >> 5, lane = tid & 31;
    int wm = w >> 2, wn = w & 3;     // 4x4 warp grid -> 32x32 region per warp
    uint32_t dsm = smem_u32(dsm_raw);

    int bi = 0, rem = blockIdx.x;
    while (rem >= NT - bi) { rem -= NT - bi; bi++; }
    int bj = bi + rem;
    int i0 = bi * 128, j0 = bj * 128;
    bool diag = (bi == bj);

    if (tid < 128) {
        sti[tid] = targets[i0 + tid];
        stj[tid] = targets[j0 + tid];
        srp[tid] = 0u;            srn[tid] = 0x7F7FFFFFu;
        scp[tid] = 0u;            scn[tid] = 0x7F7FFFFFu;
    }

    float acc[2][4][4];
    #pragma unroll
    for (int am = 0; am < 2; am++)
        #pragma unroll
        for (int bn = 0; bn < 4; bn++)
            #pragma unroll
            for (int e = 0; e < 4; e++) acc[am][bn][e] = 0.0f;

    int a_row = wm * 32 + (lane & 15);
    int a_colb = (lane >> 4) * 8;
    int b_row = wn * 32 + (lane & 7) + ((lane >> 4) << 3);
    int b_colb = ((lane >> 3) & 1) * 8;

    load_chunk(dsm, i0, j0, 0, tid);
    CP_COMMIT();

    for (int c = 0; c < NCHUNK; c++) {
        uint32_t sb = dsm + (c & 1) * STAGE_BYTES;
        if (c < NCHUNK - 1) {
            load_chunk(dsm + ((c + 1) & 1) * STAGE_BYTES, i0, j0, c + 1, tid);
            CP_COMMIT();
            CP_WAIT(1);
        } else {
            CP_WAIT(0);
        }
        __syncthreads();

        #pragma unroll
        for (int ks = 0; ks < 4; ks++) {
            int k0 = ks * 16;
            uint32_t ah[2][4], al[2][4], bh[4][2], bl[4][2];
            #pragma unroll
            for (int am = 0; am < 2; am++) {
                uint32_t off = SW128((uint32_t)((a_row + am * 16) * 128 + (k0 + a_colb) * 2));
                ldsm_x4(ah[am][0], ah[am][1], ah[am][2], ah[am][3], sb + off);
                ldsm_x4(al[am][0], al[am][1], al[am][2], al[am][3], sb + 16384 + off);
            }
            #pragma unroll
            for (int bp = 0; bp < 2; bp++) {
                uint32_t off = SW128((uint32_t)((b_row + bp * 16) * 128 + (k0 + b_colb) * 2));
                ldsm_x4(bh[bp*2][0], bh[bp*2][1], bh[bp*2+1][0], bh[bp*2+1][1], sb + 32768 + off);
                ldsm_x4(bl[bp*2][0], bl[bp*2][1], bl[bp*2+1][0], bl[bp*2+1][1], sb + 49152 + off);
            }
            #pragma unroll
            for (int am = 0; am < 2; am++)
                #pragma unroll
                for (int bn = 0; bn < 4; bn++) {
                    mma_bf16(acc[am][bn], ah[am], bh[bn]);
                    mma_bf16(acc[am][bn], ah[am], bl[bn]);
                    mma_bf16(acc[am][bn], al[am], bh[bn]);
                }
        }
        __syncthreads();
    }

    // ---- fused epilogue ----
    float posA = 0.f, negA = 0.f, semA = 0.f, qA = 0.f;
    float pm[4], nm[4], cm[8], cnn[8];
    #pragma unroll
    for (int e = 0; e < 4; e++) { pm[e] = 0.f; nm[e] = 3.4e38f; }
    #pragma unroll
    for (int e = 0; e < 8; e++) { cm[e] = 0.f; cnn[e] = 3.4e38f; }

    int r_lo = lane >> 2;
    int c_lo = (lane & 3) * 2;

    #pragma unroll
    for (int am = 0; am < 2; am++) {
        #pragma unroll
        for (int h = 0; h < 2; h++) {
            int li = wm * 32 + am * 16 + h * 8 + r_lo;
            int gi = i0 + li;
            int tiv = sti[li];
            #pragma unroll
            for (int bn = 0; bn < 4; bn++) {
                #pragma unroll
                for (int e2 = 0; e2 < 2; e2++) {
                    int lj = wn * 32 + bn * 8 + c_lo + e2;
                    int gj = j0 + lj;
                    float s = acc[am][bn][h * 2 + e2];
                    float oms = 1.0f - s;
                    float ee = oms * oms;
                    float d2 = fmaxf(2.0f - 2.0f * s, 0.0f);
                    if (diag && gi > gj) continue;
                    if (diag && gi == gj) {
                        posA += ee;
                        if (tiv == 1) semA += ee;
                        continue;
                    }
                    int tjv = stj[lj];
                    if (tiv == tjv) {
                        posA += 2.0f * ee;
                        qA += ee;
                        if (tiv == 1) semA += 2.0f * ee;
                        pm[am*2 + h] = fmaxf(pm[am*2 + h], d2);
                        cm[bn*2 + e2] = fmaxf(cm[bn*2 + e2], d2);
                    } else {
                        float cc = fmaxf(s - 0.2f, 0.0f);
                        negA += 2.0f * cc * cc;
                        nm[am*2 + h] = fminf(nm[am*2 + h], d2);
                        cnn[bn*2 + e2] = fminf(cnn[bn*2 + e2], d2);
                    }
                }
            }
        }
    }

    #pragma unroll
    for (int am = 0; am < 2; am++)
        #pragma unroll
        for (int h = 0; h < 2; h++) {
            int li = wm * 32 + am * 16 + h * 8 + r_lo;
            if (pm[am*2+h] > 0.0f)    atomicMax(&srp[li], __float_as_uint(pm[am*2+h]));
            if (nm[am*2+h] < 3.3e38f) atomicMin(&srn[li], __float_as_uint(nm[am*2+h]));
        }
    #pragma unroll
    for (int bn = 0; bn < 4; bn++)
        #pragma unroll
        for (int e2 = 0; e2 < 2; e2++) {
            int lj = wn * 32 + bn * 8 + c_lo + e2;
            if (cm[bn*2+e2] > 0.0f)     atomicMax(&scp[lj], __float_as_uint(cm[bn*2+e2]));
            if (cnn[bn*2+e2] < 3.3e38f) atomicMin(&scn[lj], __float_as_uint(cnn[bn*2+e2]));
        }
    __syncthreads();

    if (tid < 128) {
        if (srp[tid] != 0u)          atomicMax(&g_posd2[i0 + tid], srp[tid]);
        if (srn[tid] != 0x7F7FFFFFu) atomicMin(&g_negd2[i0 + tid], srn[tid]);
        if (scp[tid] != 0u)          atomicMax(&g_posd2[j0 + tid], scp[tid]);
        if (scn[tid] != 0x7F7FFFFFu) atomicMin(&g_negd2[j0 + tid], scn[tid]);
    }

    float vals[4] = {posA, negA, semA, qA};
    #pragma unroll
    for (int r = 0; r < 4; r++) {
        sredf[tid] = vals[r];
        __syncthreads();
        for (int s = GT/2; s; s >>= 1) {
            if (tid < s) sredf[tid] += sredf[tid + s];
            __syncthreads();
        }
        if (tid == 0) atomicAdd(&g_acc[r], (double)sredf[0]);
        __syncthreads();
    }

    // ---- last-block finalize ----
    __threadfence();
    __shared__ int s_rank;
    if (tid == 0) s_rank = atomicAdd(&g_done, 1);
    __syncthreads();
    if (s_rank != NBLK - 1) return;

    __shared__ double s_sum[5];
    __shared__ int    s_c[CN];
    if (w == 0) {
        double p[5];
        #pragma unroll
        for (int r = 0; r < 5; r++) p[r] = g_rows_part[lane][r];
        int c[CN];
        #pragma unroll
        for (int r = 0; r < CN; r++) c[r] = g_cnt_part[lane][r];
        #pragma unroll
        for (int r = 0; r < 5; r++) {
            double v = p[r];
            for (int o = 16; o; o >>= 1) v += __shfl_xor_sync(0xffffffffu, v, o);
            if (lane == 0) s_sum[r] = v;
        }
        #pragma unroll
        for (int r = 0; r < CN; r++) {
            int v = c[r];
            for (int o = 16; o; o >>= 1) v += __shfl_xor_sync(0xffffffffu, v, o);
            if (lane == 0) s_c[r] = v;
        }
    }
    __syncthreads();
    int c0 = s_c[0], c1 = s_c[1], c2 = s_c[2];

    __shared__ double sdd[GT];
    __shared__ int    sci[GT];
    double tsum = 0.0; int tcnt = 0;
    for (int i = tid; i < BN; i += GT) {
        int t = targets[i];
        int ct = (t == 0) ? c0 : (t == 1) ? c1 : c2;
        if ((ct >= 2) && ((BN - ct) >= 1)) {
            float hp = sqrtf(__uint_as_float(g_posd2[i]));
            float hn = sqrtf(__uint_as_float(g_negd2[i]));
            float margin = 1.5f * ((t == 1) ? 2.5f : 1.0f);
            float tl = fmaxf(hp - hn + margin, 0.0f);
            tsum += (double)tl;
            tcnt++;
        }
    }
    sdd[tid] = tsum; sci[tid] = tcnt;
    __syncthreads();
    for (int s = GT/2; s; s >>= 1) {
        if (tid < s) { sdd[tid] += sdd[tid + s]; sci[tid] += sci[tid + s]; }
        __syncthreads();
    }
    if (tid == 0) {
        double triplet = (sci[0] > 0) ? sdd[0] / (double)(sci[0] > 1 ? sci[0] : 1) : 0.0;
        double focal = s_sum[0] / (double)BN;
        double wsum = (double)c0*cw[0] + (double)c1*cw[1] + (double)c2*cw[2];
        double ce = s_sum[1] / wsum;
        double boundary = s_sum[2] / ((double)BN + 1e-8);
        double contrastive = (g_acc[0] + g_acc[1] + 4.0*g_acc[2]) / ((double)BN*(double)BN + 1e-8);
        long long sp = (long long)c0*c0 + (long long)c1*c1 + (long long)c2*c2;
        long long npairs = (sp - BN) / 2;
        double q = g_acc[3] / (double)(npairs > 1 ? npairs : 1);
        if (c2 > 0) q *= 1.0 + 2.5 * ((double)c2 / (double)BN);
        double quality = (npairs > 0) ? q : 0.0;
        int epoch = epoch_p[0];
        double ann = (double)epoch / 25.0; ann *= ann; if (ann > 1.0) ann = 1.0;
        double evid = s_sum[3] / (double)BN + ann * 0.2 * (s_sum[4] / (double)BN);
        out[0] = (float)(0.4*focal + 0.3*ce + 0.15*boundary
                       + 0.1*contrastive + 0.1*triplet + 0.1*quality + 0.1*evid);
    }
}

// ---------------- launcher ----------------
extern "C" void kernel_launch(void* const* d_in, const int* in_sizes, int n_in,
                              void* d_out, int out_size) {
    const float* logits   = (const float*)d_in[0];
    const int*   targets  = (const int*)d_in[1];
    const float* features = (const float*)d_in[2];
    const float* alpha    = (const float*)d_in[3];
    const int*   epoch    = (const int*)d_in[4];
    const float* fa       = (const float*)d_in[5];
    const float* cw       = (const float*)d_in[6];
    float* out = (float*)d_out;

    cudaFuncSetAttribute(k_gram, cudaFuncAttributeMaxDynamicSharedMemorySize, DSMEM_BYTES);

    k_prep<<<BN + NRB, 128>>>(features, logits, targets, alpha, fa, cw);
    k_gram<<<NBLK, GT, DSMEM_BYTES>>>(targets, cw, epoch, out);
}

// round 7
// speedup vs baseline: 6.5062x; 1.1718x over previous
#include <cuda_runtime.h>
#include <cuda_fp16.h>
#include <math.h>
#include <stdint.h>

#define BN 4096
#define DN 512
#define CN 3
#define NT 32                       // 4096/128 tiles per dim
#define NBLK (NT * (NT + 1) / 2)    // 528 upper-tri tile pairs
#define NCHUNK 8                    // K chunks of 64
#define STAGE_BYTES 49152           // 3 tiles x 16KB (A_hi, A_lo, B_hi)
#define DSMEM_BYTES (2 * STAGE_BYTES)
#define NRB 32                      // row-scalar blocks (128 thr each)
#define GT 512                      // k_gram threads

// ---------------- device scratch ----------------
__device__ __align__(16) __half g_hi[BN * DN];
__device__ __align__(16) __half g_lo[BN * DN];
__device__ unsigned int g_posd2[BN];
__device__ unsigned int g_negd2[BN];
__device__ double       g_acc[4];            // 0 pos 1 neg 2 semi 3 q
__device__ double       g_rows_part[NRB][5];
__device__ int          g_cnt_part[NRB][CN];
__device__ int          g_done;

// ---------------- PTX helpers (base sm_103-legal only) ----------------
__device__ __forceinline__ uint32_t smem_u32(const void* p) {
    uint32_t a;
    asm("{ .reg .u64 t; cvta.to.shared.u64 t, %1; cvt.u32.u64 %0, t; }" : "=r"(a) : "l"(p));
    return a;
}
#define SW128(x) ((x) ^ (((x) >> 3) & 0x70))

__device__ __forceinline__ void cp16(uint32_t smem, const void* g) {
    asm volatile("cp.async.cg.shared.global [%0], [%1], 16;" :: "r"(smem), "l"(g));
}
#define CP_COMMIT()  asm volatile("cp.async.commit_group;" ::: "memory")
#define CP_WAIT(n)   asm volatile("cp.async.wait_group %0;" :: "n"(n) : "memory")

__device__ __forceinline__ void ldsm_x4(uint32_t& r0, uint32_t& r1, uint32_t& r2, uint32_t& r3,
                                        uint32_t addr) {
    asm volatile("ldmatrix.sync.aligned.m8n8.x4.shared.b16 {%0,%1,%2,%3}, [%4];"
                 : "=r"(r0), "=r"(r1), "=r"(r2), "=r"(r3) : "r"(addr));
}

__device__ __forceinline__ void mma_f16(float* c, const uint32_t* a, const uint32_t* b) {
    asm volatile("mma.sync.aligned.m16n8k16.row.col.f32.f16.f16.f32 "
                 "{%0,%1,%2,%3}, {%4,%5,%6,%7}, {%8,%9}, {%0,%1,%2,%3};"
                 : "+f"(c[0]), "+f"(c[1]), "+f"(c[2]), "+f"(c[3])
                 : "r"(a[0]), "r"(a[1]), "r"(a[2]), "r"(a[3]), "r"(b[0]), "r"(b[1]));
}

// ---------------- misc helpers ----------------
__device__ __forceinline__ float digamma_f(float x) {
    float r = 0.0f;
    while (x < 6.0f) { r -= 1.0f / x; x += 1.0f; }
    float f = 1.0f / (x * x);
    return logf(x) - 0.5f / x
        - f * (1.0f/12.0f - f * (1.0f/120.0f - f * (1.0f/252.0f - f * (1.0f/240.0f))))
        + r;
}

// ---------------- prep kernel ----------------
__global__ void k_prep(const float* __restrict__ f, const float* __restrict__ logits,
                       const int* __restrict__ targets, const float* __restrict__ alpha,
                       const float* __restrict__ fa, const float* __restrict__ cw) {
    int tid = threadIdx.x;
    if (blockIdx.x < BN) {
        int row = blockIdx.x;
        float4 v = ((const float4*)(f + (size_t)row * DN))[tid];
        float ss = v.x*v.x + v.y*v.y + v.z*v.z + v.w*v.w;
        for (int o = 16; o; o >>= 1) ss += __shfl_xor_sync(0xffffffffu, ss, o);
        __shared__ float sred[4];
        if ((tid & 31) == 0) sred[tid >> 5] = ss;
        __syncthreads();
        __shared__ float sinv;
        if (tid == 0) {
            float n = sqrtf(sred[0] + sred[1] + sred[2] + sred[3]);
            sinv = 1.0f / fmaxf(n, 1e-12f);
        }
        __syncthreads();
        float inv = sinv;
        float x0 = v.x*inv, x1 = v.y*inv, x2 = v.z*inv, x3 = v.w*inv;
        __half h0 = __float2half_rn(x0), h1 = __float2half_rn(x1);
        __half h2 = __float2half_rn(x2), h3 = __float2half_rn(x3);
        __half l0 = __float2half_rn(x0 - __half2float(h0));
        __half l1 = __float2half_rn(x1 - __half2float(h1));
        __half l2 = __float2half_rn(x2 - __half2float(h2));
        __half l3 = __float2half_rn(x3 - __half2float(h3));
        uint2 hv, lv;
        hv.x = (uint32_t)__half_as_ushort(h0) | ((uint32_t)__half_as_ushort(h1) << 16);
        hv.y = (uint32_t)__half_as_ushort(h2) | ((uint32_t)__half_as_ushort(h3) << 16);
        lv.x = (uint32_t)__half_as_ushort(l0) | ((uint32_t)__half_as_ushort(l1) << 16);
        lv.y = (uint32_t)__half_as_ushort(l2) | ((uint32_t)__half_as_ushort(l3) << 16);
        ((uint2*)g_hi)[(size_t)row * 128 + tid] = hv;
        ((uint2*)g_lo)[(size_t)row * 128 + tid] = lv;

        if (tid == 0) { g_posd2[row] = 0u; g_negd2[row] = 0x7F7FFFFFu; }
        if (row == 0) {
            if (tid < 4) g_acc[tid] = 0.0;
            if (tid == 4) g_done = 0;
        }
    } else {
        int rb = blockIdx.x - BN;
        int i = rb * 128 + tid;
        int t = targets[i];

        float l0 = logits[3*i], l1 = logits[3*i+1], l2 = logits[3*i+2];
        float m  = fmaxf(l0, fmaxf(l1, l2));
        float e0 = expf(l0-m), e1 = expf(l1-m), e2 = expf(l2-m);
        float Z  = e0 + e1 + e2;
        float lse = m + logf(Z);
        float lp0 = l0-lse, lp1 = l1-lse, lp2 = l2-lse;
        float lpt = (t == 0) ? lp0 : (t == 1) ? lp1 : lp2;
        float nll = -lpt;
        float ce_ls = 0.9f * nll - 0.1f * ((lp0+lp1+lp2) * (1.0f/3.0f));
        float pt = expf(-ce_ls);
        float om = 1.0f - pt;
        float fterm = fa[t] * om * om * ce_ls;
        float wnll  = cw[t] * nll;
        float p0 = e0/Z, p1 = e1/Z, p2 = e2/Z;
        float bterm = (t == 0) ? (p1 + 0.6f*p2)
                    : (t == 2) ? (p1 + 0.4f*p0)
                    :            4.5f * (1.0f - p1 + 0.3f*(p0 + p2));

        float a0 = alpha[3*i], a1 = alpha[3*i+1], a2 = alpha[3*i+2];
        float S  = a0 + a1 + a2 + 1e-8f;
        float at = (t == 0) ? a0 : (t == 1) ? a1 : a2;
        float lik = digamma_f(S) - digamma_f(at + 1e-8f);
        float b0 = (t == 0) ? 1.0f : a0;
        float b1 = (t == 1) ? 1.0f : a1;
        float b2 = (t == 2) ? 1.0f : a2;
        float ats = b0 + b1 + b2 + 1e-8f;
        float dga = digamma_f(ats + 1e-8f);
        float kl = lgammaf(ats) - (lgammaf(b0+1e-8f) + lgammaf(b1+1e-8f) + lgammaf(b2+1e-8f))
                 + (b0-1.0f) * (digamma_f(b0+1e-8f) - dga)
                 + (b1-1.0f) * (digamma_f(b1+1e-8f) - dga)
                 + (b2-1.0f) * (digamma_f(b2+1e-8f) - dga);

        double vals[5] = { (double)fterm, (double)wnll, (double)bterm, (double)lik, (double)kl };
        __shared__ double swp[4][5];
        int lane = tid & 31, w = tid >> 5;
        #pragma unroll
        for (int r = 0; r < 5; r++) {
            double v = vals[r];
            for (int o = 16; o; o >>= 1) v += __shfl_xor_sync(0xffffffffu, v, o);
            if (lane == 0) swp[w][r] = v;
        }
        __shared__ int sh[CN];
        if (tid < CN) sh[tid] = 0;
        __syncthreads();
        atomicAdd(&sh[t], 1);
        __syncthreads();
        if (tid < 5)  g_rows_part[rb][tid] = swp[0][tid] + swp[1][tid] + swp[2][tid] + swp[3][tid];
        if (tid < CN) g_cnt_part[rb][tid] = sh[tid];
    }
}

// gmem -> smem stage loader (cp.async): A_hi, A_lo, B_hi — 6 x 16B per thread
__device__ __forceinline__ void load_chunk(uint32_t sb, int i0, int j0, int c, int tid) {
    const uint4* gh4 = (const uint4*)g_hi;
    const uint4* gl4 = (const uint4*)g_lo;
    #pragma unroll
    for (int p = 0; p < 2; p++) {
        int lin = p * GT + tid;
        int r = lin >> 3, q = lin & 7;
        uint32_t so = SW128((uint32_t)(r * 128 + q * 16));
        size_t si = (size_t)(i0 + r) * 64 + c * 8 + q;
        size_t sj = (size_t)(j0 + r) * 64 + c * 8 + q;
        cp16(sb +         so, gh4 + si);
        cp16(sb + 16384 + so, gl4 + si);
        cp16(sb + 32768 + so, gh4 + sj);
    }
}

// HMMA Gram kernel (512 thr, warp grid 4x4, warp tile 32x32) + last-block finalize
__global__ void __launch_bounds__(GT, 1) k_gram(const int* __restrict__ targets,
                                                const float* __restrict__ cw,
                                                const int* __restrict__ epoch_p,
                                                float* __restrict__ out) {
    extern __shared__ __align__(1024) char dsm_raw[];
    __shared__ int sti[128], stj[128];
    __shared__ unsigned int srp[128], srn[128], scp[128], scn[128];
    __shared__ float sredf[GT];

    int tid = threadIdx.x;
    int w = tid >> 5, lane = tid & 31;
    int wm = w >> 2, wn = w & 3;     // 4x4 warp grid -> 32x32 region per warp
    uint32_t dsm = smem_u32(dsm_raw);

    int bi = 0, rem = blockIdx.x;
    while (rem >= NT - bi) { rem -= NT - bi; bi++; }
    int bj = bi + rem;
    int i0 = bi * 128, j0 = bj * 128;
    bool diag = (bi == bj);

    if (tid < 128) {
        sti[tid] = targets[i0 + tid];
        stj[tid] = targets[j0 + tid];
        srp[tid] = 0u;            srn[tid] = 0x7F7FFFFFu;
        scp[tid] = 0u;            scn[tid] = 0x7F7FFFFFu;
    }

    float acc[2][4][4];
    #pragma unroll
    for (int am = 0; am < 2; am++)
        #pragma unroll
        for (int bn = 0; bn < 4; bn++)
            #pragma unroll
            for (int e = 0; e < 4; e++) acc[am][bn][e] = 0.0f;

    int a_row = wm * 32 + (lane & 15);
    int a_colb = (lane >> 4) * 8;
    int b_row = wn * 32 + (lane & 7) + ((lane >> 4) << 3);
    int b_colb = ((lane >> 3) & 1) * 8;

    load_chunk(dsm, i0, j0, 0, tid);
    CP_COMMIT();

    for (int c = 0; c < NCHUNK; c++) {
        uint32_t sb = dsm + (c & 1) * STAGE_BYTES;
        if (c < NCHUNK - 1) {
            load_chunk(dsm + ((c + 1) & 1) * STAGE_BYTES, i0, j0, c + 1, tid);
            CP_COMMIT();
            CP_WAIT(1);
        } else {
            CP_WAIT(0);
        }
        __syncthreads();

        #pragma unroll
        for (int ks = 0; ks < 4; ks++) {
            int k0 = ks * 16;
            uint32_t ah[2][4], al[2][4], bh[4][2];
            #pragma unroll
            for (int am = 0; am < 2; am++) {
                uint32_t off = SW128((uint32_t)((a_row + am * 16) * 128 + (k0 + a_colb) * 2));
                ldsm_x4(ah[am][0], ah[am][1], ah[am][2], ah[am][3], sb + off);
                ldsm_x4(al[am][0], al[am][1], al[am][2], al[am][3], sb + 16384 + off);
            }
            #pragma unroll
            for (int bp = 0; bp < 2; bp++) {
                uint32_t off = SW128((uint32_t)((b_row + bp * 16) * 128 + (k0 + b_colb) * 2));
                ldsm_x4(bh[bp*2][0], bh[bp*2][1], bh[bp*2+1][0], bh[bp*2+1][1], sb + 32768 + off);
            }
            #pragma unroll
            for (int am = 0; am < 2; am++)
                #pragma unroll
                for (int bn = 0; bn < 4; bn++) {
                    mma_f16(acc[am][bn], ah[am], bh[bn]);
                    mma_f16(acc[am][bn], al[am], bh[bn]);
                }
        }
        __syncthreads();
    }

    // ---- fused epilogue ----
    float posA = 0.f, negA = 0.f, semA = 0.f, qA = 0.f;
    float pm[4], nm[4], cm[8], cnn[8];
    #pragma unroll
    for (int e = 0; e < 4; e++) { pm[e] = 0.f; nm[e] = 3.4e38f; }
    #pragma unroll
    for (int e = 0; e < 8; e++) { cm[e] = 0.f; cnn[e] = 3.4e38f; }

    int r_lo = lane >> 2;
    int c_lo = (lane & 3) * 2;

    #pragma unroll
    for (int am = 0; am < 2; am++) {
        #pragma unroll
        for (int h = 0; h < 2; h++) {
            int li = wm * 32 + am * 16 + h * 8 + r_lo;
            int gi = i0 + li;
            int tiv = sti[li];
            #pragma unroll
            for (int bn = 0; bn < 4; bn++) {
                #pragma unroll
                for (int e2 = 0; e2 < 2; e2++) {
                    int lj = wn * 32 + bn * 8 + c_lo + e2;
                    int gj = j0 + lj;
                    float s = acc[am][bn][h * 2 + e2];
                    float oms = 1.0f - s;
                    float ee = oms * oms;
                    float d2 = fmaxf(2.0f - 2.0f * s, 0.0f);
                    if (diag && gi > gj) continue;
                    if (diag && gi == gj) {
                        posA += ee;
                        if (tiv == 1) semA += ee;
                        continue;
                    }
                    int tjv = stj[lj];
                    if (tiv == tjv) {
                        posA += 2.0f * ee;
                        qA += ee;
                        if (tiv == 1) semA += 2.0f * ee;
                        pm[am*2 + h] = fmaxf(pm[am*2 + h], d2);
                        cm[bn*2 + e2] = fmaxf(cm[bn*2 + e2], d2);
                    } else {
                        float cc = fmaxf(s - 0.2f, 0.0f);
                        negA += 2.0f * cc * cc;
                        nm[am*2 + h] = fminf(nm[am*2 + h], d2);
                        cnn[bn*2 + e2] = fminf(cnn[bn*2 + e2], d2);
                    }
                }
            }
        }
    }

    #pragma unroll
    for (int am = 0; am < 2; am++)
        #pragma unroll
        for (int h = 0; h < 2; h++) {
            int li = wm * 32 + am * 16 + h * 8 + r_lo;
            if (pm[am*2+h] > 0.0f)    atomicMax(&srp[li], __float_as_uint(pm[am*2+h]));
            if (nm[am*2+h] < 3.3e38f) atomicMin(&srn[li], __float_as_uint(nm[am*2+h]));
        }
    #pragma unroll
    for (int bn = 0; bn < 4; bn++)
        #pragma unroll
        for (int e2 = 0; e2 < 2; e2++) {
            int lj = wn * 32 + bn * 8 + c_lo + e2;
            if (cm[bn*2+e2] > 0.0f)     atomicMax(&scp[lj], __float_as_uint(cm[bn*2+e2]));
            if (cnn[bn*2+e2] < 3.3e38f) atomicMin(&scn[lj], __float_as_uint(cnn[bn*2+e2]));
        }
    __syncthreads();

    if (tid < 128) {
        if (srp[tid] != 0u)          atomicMax(&g_posd2[i0 + tid], srp[tid]);
        if (srn[tid] != 0x7F7FFFFFu) atomicMin(&g_negd2[i0 + tid], srn[tid]);
        if (scp[tid] != 0u)          atomicMax(&g_posd2[j0 + tid], scp[tid]);
        if (scn[tid] != 0x7F7FFFFFu) atomicMin(&g_negd2[j0 + tid], scn[tid]);
    }

    float vals[4] = {posA, negA, semA, qA};
    #pragma unroll
    for (int r = 0; r < 4; r++) {
        sredf[tid] = vals[r];
        __syncthreads();
        for (int s = GT/2; s; s >>= 1) {
            if (tid < s) sredf[tid] += sredf[tid + s];
            __syncthreads();
        }
        if (tid == 0) atomicAdd(&g_acc[r], (double)sredf[0]);
        __syncthreads();
    }

    // ---- last-block finalize ----
    __threadfence();
    __shared__ int s_rank;
    if (tid == 0) s_rank = atomicAdd(&g_done, 1);
    __syncthreads();
    if (s_rank != NBLK - 1) return;

    __shared__ double s_sum[5];
    __shared__ int    s_c[CN];
    if (w == 0) {
        double p[5];
        #pragma unroll
        for (int r = 0; r < 5; r++) p[r] = g_rows_part[lane][r];
        int c[CN];
        #pragma unroll
        for (int r = 0; r < CN; r++) c[r] = g_cnt_part[lane][r];
        #pragma unroll
        for (int r = 0; r < 5; r++) {
            double v = p[r];
            for (int o = 16; o; o >>= 1) v += __shfl_xor_sync(0xffffffffu, v, o);
            if (lane == 0) s_sum[r] = v;
        }
        #pragma unroll
        for (int r = 0; r < CN; r++) {
            int v = c[r];
            for (int o = 16; o; o >>= 1) v += __shfl_xor_sync(0xffffffffu, v, o);
            if (lane == 0) s_c[r] = v;
        }
    }
    __syncthreads();
    int c0 = s_c[0], c1 = s_c[1], c2 = s_c[2];

    __shared__ double sdd[GT];
    __shared__ int    sci[GT];
    double tsum = 0.0; int tcnt = 0;
    for (int i = tid; i < BN; i += GT) {
        int t = targets[i];
        int ct = (t == 0) ? c0 : (t == 1) ? c1 : c2;
        if ((ct >= 2) && ((BN - ct) >= 1)) {
            float hp = sqrtf(__uint_as_float(g_posd2[i]));
            float hn = sqrtf(__uint_as_float(g_negd2[i]));
            float margin = 1.5f * ((t == 1) ? 2.5f : 1.0f);
            float tl = fmaxf(hp - hn + margin, 0.0f);
            tsum += (double)tl;
            tcnt++;
        }
    }
    sdd[tid] = tsum; sci[tid] = tcnt;
    __syncthreads();
    for (int s = GT/2; s; s >>= 1) {
        if (tid < s) { sdd[tid] += sdd[tid + s]; sci[tid] += sci[tid + s]; }
        __syncthreads();
    }
    if (tid == 0) {
        double triplet = (sci[0] > 0) ? sdd[0] / (double)(sci[0] > 1 ? sci[0] : 1) : 0.0;
        double focal = s_sum[0] / (double)BN;
        double wsum = (double)c0*cw[0] + (double)c1*cw[1] + (double)c2*cw[2];
        double ce = s_sum[1] / wsum;
        double boundary = s_sum[2] / ((double)BN + 1e-8);
        double contrastive = (g_acc[0] + g_acc[1] + 4.0*g_acc[2]) / ((double)BN*(double)BN + 1e-8);
        long long sp = (long long)c0*c0 + (long long)c1*c1 + (long long)c2*c2;
        long long npairs = (sp - BN) / 2;
        double q = g_acc[3] / (double)(npairs > 1 ? npairs : 1);
        if (c2 > 0) q *= 1.0 + 2.5 * ((double)c2 / (double)BN);
        double quality = (npairs > 0) ? q : 0.0;
        int epoch = epoch_p[0];
        double ann = (double)epoch / 25.0; ann *= ann; if (ann > 1.0) ann = 1.0;
        double evid = s_sum[3] / (double)BN + ann * 0.2 * (s_sum[4] / (double)BN);
        out[0] = (float)(0.4*focal + 0.3*ce + 0.15*boundary
                       + 0.1*contrastive + 0.1*triplet + 0.1*quality + 0.1*evid);
    }
}

// ---------------- launcher ----------------
extern "C" void kernel_launch(void* const* d_in, const int* in_sizes, int n_in,
                              void* d_out, int out_size) {
    const float* logits   = (const float*)d_in[0];
    const int*   targets  = (const int*)d_in[1];
    const float* features = (const float*)d_in[2];
    const float* alpha    = (const float*)d_in[3];
    const int*   epoch    = (const int*)d_in[4];
    const float* fa       = (const float*)d_in[5];
    const float* cw       = (const float*)d_in[6];
    float* out = (float*)d_out;

    cudaFuncSetAttribute(k_gram, cudaFuncAttributeMaxDynamicSharedMemorySize, DSMEM_BYTES);

    k_prep<<<BN + NRB, 128>>>(features, logits, targets, alpha, fa, cw);
    k_gram<<<NBLK, GT, DSMEM_BYTES>>>(targets, cw, epoch, out);
}

// round 8
// speedup vs baseline: 7.4304x; 1.1420x over previous
#include <cuda_runtime.h>
#include <cuda_fp16.h>
#include <math.h>
#include <stdint.h>

#define BN 4096
#define DN 512
#define CN 3
#define NT 32                       // 4096/128 tiles per dim
#define NBLK (NT * (NT + 1) / 2)    // 528 upper-tri tile pairs
#define NCHUNK 8                    // K chunks of 64
#define STAGE_BYTES 49152           // 3 tiles x 16KB (A_hi, A_lo, B_hi)
#define NSTAGE 3
#define DSMEM_BYTES (NSTAGE * STAGE_BYTES)
#define NRB 32                      // row-scalar blocks (128 thr each)
#define GT 512                      // k_gram threads
#define NPERS 148                   // persistent CTAs

// ---------------- device scratch ----------------
__device__ __align__(16) __half g_hi[BN * DN];
__device__ __align__(16) __half g_lo[BN * DN];
__device__ unsigned int g_posd2[BN];
__device__ unsigned int g_negd2[BN];
__device__ double       g_acc[4];            // 0 pos 1 neg 2 semi 3 q
__device__ double       g_rows_part[NRB][5];
__device__ int          g_cnt_part[NRB][CN];
__device__ int          g_done;
__device__ int          g_work;

// ---------------- PTX helpers (base sm_103-legal only) ----------------
__device__ __forceinline__ uint32_t smem_u32(const void* p) {
    uint32_t a;
    asm("{ .reg .u64 t; cvta.to.shared.u64 t, %1; cvt.u32.u64 %0, t; }" : "=r"(a) : "l"(p));
    return a;
}
#define SW128(x) ((x) ^ (((x) >> 3) & 0x70))

__device__ __forceinline__ void cp16(uint32_t smem, const void* g) {
    asm volatile("cp.async.cg.shared.global [%0], [%1], 16;" :: "r"(smem), "l"(g));
}
#define CP_COMMIT()  asm volatile("cp.async.commit_group;" ::: "memory")
#define CP_WAIT(n)   asm volatile("cp.async.wait_group %0;" :: "n"(n) : "memory")

__device__ __forceinline__ void ldsm_x4(uint32_t& r0, uint32_t& r1, uint32_t& r2, uint32_t& r3,
                                        uint32_t addr) {
    asm volatile("ldmatrix.sync.aligned.m8n8.x4.shared.b16 {%0,%1,%2,%3}, [%4];"
                 : "=r"(r0), "=r"(r1), "=r"(r2), "=r"(r3) : "r"(addr));
}

__device__ __forceinline__ void mma_f16(float* c, const uint32_t* a, const uint32_t* b) {
    asm volatile("mma.sync.aligned.m16n8k16.row.col.f32.f16.f16.f32 "
                 "{%0,%1,%2,%3}, {%4,%5,%6,%7}, {%8,%9}, {%0,%1,%2,%3};"
                 : "+f"(c[0]), "+f"(c[1]), "+f"(c[2]), "+f"(c[3])
                 : "r"(a[0]), "r"(a[1]), "r"(a[2]), "r"(a[3]), "r"(b[0]), "r"(b[1]));
}

// ---------------- misc helpers ----------------
__device__ __forceinline__ float digamma_f(float x) {
    float r = 0.0f;
    while (x < 6.0f) { r -= 1.0f / x; x += 1.0f; }
    float f = 1.0f / (x * x);
    return logf(x) - 0.5f / x
        - f * (1.0f/12.0f - f * (1.0f/120.0f - f * (1.0f/252.0f - f * (1.0f/240.0f))))
        + r;
}

// ---------------- prep kernel ----------------
__global__ void k_prep(const float* __restrict__ f, const float* __restrict__ logits,
                       const int* __restrict__ targets, const float* __restrict__ alpha,
                       const float* __restrict__ fa, const float* __restrict__ cw) {
    int tid = threadIdx.x;
    if (blockIdx.x < BN) {
        int row = blockIdx.x;
        float4 v = ((const float4*)(f + (size_t)row * DN))[tid];
        float ss = v.x*v.x + v.y*v.y + v.z*v.z + v.w*v.w;
        for (int o = 16; o; o >>= 1) ss += __shfl_xor_sync(0xffffffffu, ss, o);
        __shared__ float sred[4];
        if ((tid & 31) == 0) sred[tid >> 5] = ss;
        __syncthreads();
        __shared__ float sinv;
        if (tid == 0) {
            float n = sqrtf(sred[0] + sred[1] + sred[2] + sred[3]);
            sinv = 1.0f / fmaxf(n, 1e-12f);
        }
        __syncthreads();
        float inv = sinv;
        float x0 = v.x*inv, x1 = v.y*inv, x2 = v.z*inv, x3 = v.w*inv;
        __half h0 = __float2half_rn(x0), h1 = __float2half_rn(x1);
        __half h2 = __float2half_rn(x2), h3 = __float2half_rn(x3);
        __half l0 = __float2half_rn(x0 - __half2float(h0));
        __half l1 = __float2half_rn(x1 - __half2float(h1));
        __half l2 = __float2half_rn(x2 - __half2float(h2));
        __half l3 = __float2half_rn(x3 - __half2float(h3));
        uint2 hv, lv;
        hv.x = (uint32_t)__half_as_ushort(h0) | ((uint32_t)__half_as_ushort(h1) << 16);
        hv.y = (uint32_t)__half_as_ushort(h2) | ((uint32_t)__half_as_ushort(h3) << 16);
        lv.x = (uint32_t)__half_as_ushort(l0) | ((uint32_t)__half_as_ushort(l1) << 16);
        lv.y = (uint32_t)__half_as_ushort(l2) | ((uint32_t)__half_as_ushort(l3) << 16);
        ((uint2*)g_hi)[(size_t)row * 128 + tid] = hv;
        ((uint2*)g_lo)[(size_t)row * 128 + tid] = lv;

        if (tid == 0) { g_posd2[row] = 0u; g_negd2[row] = 0x7F7FFFFFu; }
        if (row == 0) {
            if (tid < 4) g_acc[tid] = 0.0;
            if (tid == 4) g_done = 0;
            if (tid == 5) g_work = 0;
        }
    } else {
        int rb = blockIdx.x - BN;
        int i = rb * 128 + tid;
        int t = targets[i];

        float l0 = logits[3*i], l1 = logits[3*i+1], l2 = logits[3*i+2];
        float m  = fmaxf(l0, fmaxf(l1, l2));
        float e0 = expf(l0-m), e1 = expf(l1-m), e2 = expf(l2-m);
        float Z  = e0 + e1 + e2;
        float lse = m + logf(Z);
        float lp0 = l0-lse, lp1 = l1-lse, lp2 = l2-lse;
        float lpt = (t == 0) ? lp0 : (t == 1) ? lp1 : lp2;
        float nll = -lpt;
        float ce_ls = 0.9f * nll - 0.1f * ((lp0+lp1+lp2) * (1.0f/3.0f));
        float pt = expf(-ce_ls);
        float om = 1.0f - pt;
        float fterm = fa[t] * om * om * ce_ls;
        float wnll  = cw[t] * nll;
        float p0 = e0/Z, p1 = e1/Z, p2 = e2/Z;
        float bterm = (t == 0) ? (p1 + 0.6f*p2)
                    : (t == 2) ? (p1 + 0.4f*p0)
                    :            4.5f * (1.0f - p1 + 0.3f*(p0 + p2));

        float a0 = alpha[3*i], a1 = alpha[3*i+1], a2 = alpha[3*i+2];
        float S  = a0 + a1 + a2 + 1e-8f;
        float at = (t == 0) ? a0 : (t == 1) ? a1 : a2;
        float lik = digamma_f(S) - digamma_f(at + 1e-8f);
        float b0 = (t == 0) ? 1.0f : a0;
        float b1 = (t == 1) ? 1.0f : a1;
        float b2 = (t == 2) ? 1.0f : a2;
        float ats = b0 + b1 + b2 + 1e-8f;
        float dga = digamma_f(ats + 1e-8f);
        float kl = lgammaf(ats) - (lgammaf(b0+1e-8f) + lgammaf(b1+1e-8f) + lgammaf(b2+1e-8f))
                 + (b0-1.0f) * (digamma_f(b0+1e-8f) - dga)
                 + (b1-1.0f) * (digamma_f(b1+1e-8f) - dga)
                 + (b2-1.0f) * (digamma_f(b2+1e-8f) - dga);

        double vals[5] = { (double)fterm, (double)wnll, (double)bterm, (double)lik, (double)kl };
        __shared__ double swp[4][5];
        int lane = tid & 31, w = tid >> 5;
        #pragma unroll
        for (int r = 0; r < 5; r++) {
            double v = vals[r];
            for (int o = 16; o; o >>= 1) v += __shfl_xor_sync(0xffffffffu, v, o);
            if (lane == 0) swp[w][r] = v;
        }
        __shared__ int sh[CN];
        if (tid < CN) sh[tid] = 0;
        __syncthreads();
        atomicAdd(&sh[t], 1);
        __syncthreads();
        if (tid < 5)  g_rows_part[rb][tid] = swp[0][tid] + swp[1][tid] + swp[2][tid] + swp[3][tid];
        if (tid < CN) g_cnt_part[rb][tid] = sh[tid];
    }
}

// gmem -> smem stage loader (cp.async): A_hi, A_lo, B_hi — 6 x 16B per thread
__device__ __forceinline__ void load_chunk(uint32_t sb, int i0, int j0, int c, int tid) {
    const uint4* gh4 = (const uint4*)g_hi;
    const uint4* gl4 = (const uint4*)g_lo;
    #pragma unroll
    for (int p = 0; p < 2; p++) {
        int lin = p * GT + tid;
        int r = lin >> 3, q = lin & 7;
        uint32_t so = SW128((uint32_t)(r * 128 + q * 16));
        size_t si = (size_t)(i0 + r) * 64 + c * 8 + q;
        size_t sj = (size_t)(j0 + r) * 64 + c * 8 + q;
        cp16(sb +         so, gh4 + si);
        cp16(sb + 16384 + so, gl4 + si);
        cp16(sb + 32768 + so, gh4 + sj);
    }
}

// persistent HMMA Gram kernel + last-CTA finalize
__global__ void __launch_bounds__(GT, 1) k_gram(const int* __restrict__ targets,
                                                const float* __restrict__ cw,
                                                const int* __restrict__ epoch_p,
                                                float* __restrict__ out) {
    extern __shared__ __align__(1024) char dsm_raw[];
    __shared__ int sti[128], stj[128];
    __shared__ unsigned int srp[128], srn[128], scp[128], scn[128];
    __shared__ float sredf[GT];
    __shared__ int s_tile;

    int tid = threadIdx.x;
    int w = tid >> 5, lane = tid & 31;
    int wm = w >> 2, wn = w & 3;     // 4x4 warp grid -> 32x32 region per warp
    uint32_t dsm = smem_u32(dsm_raw);

    int a_row = wm * 32 + (lane & 15);
    int a_colb = (lane >> 4) * 8;
    int b_row = wn * 32 + (lane & 7) + ((lane >> 4) << 3);
    int b_colb = ((lane >> 3) & 1) * 8;
    int r_lo = lane >> 2;
    int c_lo = (lane & 3) * 2;

    // cross-tile accumulators (reduced once at the end)
    float posA = 0.f, negA = 0.f, semA = 0.f, qA = 0.f;

    for (;;) {
        if (tid == 0) s_tile = atomicAdd(&g_work, 1);
        __syncthreads();   // broadcasts s_tile; also separates prior tile's smem use
        int tile = s_tile;
        if (tile >= NBLK) break;

        int bi = 0, rem = tile;
        while (rem >= NT - bi) { rem -= NT - bi; bi++; }
        int bj = bi + rem;
        int i0 = bi * 128, j0 = bj * 128;
        bool diag = (bi == bj);

        if (tid < 128) {
            sti[tid] = targets[i0 + tid];
            stj[tid] = targets[j0 + tid];
            srp[tid] = 0u;            srn[tid] = 0x7F7FFFFFu;
            scp[tid] = 0u;            scn[tid] = 0x7F7FFFFFu;
        }

        float acc[2][4][4];
        #pragma unroll
        for (int am = 0; am < 2; am++)
            #pragma unroll
            for (int bn = 0; bn < 4; bn++)
                #pragma unroll
                for (int e = 0; e < 4; e++) acc[am][bn][e] = 0.0f;

        load_chunk(dsm,               i0, j0, 0, tid); CP_COMMIT();
        load_chunk(dsm + STAGE_BYTES, i0, j0, 1, tid); CP_COMMIT();

        #pragma unroll
        for (int c = 0; c < NCHUNK; c++) {
            if (c < NCHUNK - 1) CP_WAIT(1); else CP_WAIT(0);
            __syncthreads();   // chunk c resident; stage (c-1)%3 free for reuse
            if (c < NCHUNK - 2) {
                load_chunk(dsm + ((c + 2) % NSTAGE) * STAGE_BYTES, i0, j0, c + 2, tid);
                CP_COMMIT();
            }
            uint32_t sb = dsm + (c % NSTAGE) * STAGE_BYTES;

            #pragma unroll
            for (int ks = 0; ks < 4; ks++) {
                int k0 = ks * 16;
                uint32_t ah[2][4], al[2][4], bh[4][2];
                #pragma unroll
                for (int am = 0; am < 2; am++) {
                    uint32_t off = SW128((uint32_t)((a_row + am * 16) * 128 + (k0 + a_colb) * 2));
                    ldsm_x4(ah[am][0], ah[am][1], ah[am][2], ah[am][3], sb + off);
                    ldsm_x4(al[am][0], al[am][1], al[am][2], al[am][3], sb + 16384 + off);
                }
                #pragma unroll
                for (int bp = 0; bp < 2; bp++) {
                    uint32_t off = SW128((uint32_t)((b_row + bp * 16) * 128 + (k0 + b_colb) * 2));
                    ldsm_x4(bh[bp*2][0], bh[bp*2][1], bh[bp*2+1][0], bh[bp*2+1][1], sb + 32768 + off);
                }
                #pragma unroll
                for (int am = 0; am < 2; am++)
                    #pragma unroll
                    for (int bn = 0; bn < 4; bn++) {
                        mma_f16(acc[am][bn], ah[am], bh[bn]);
                        mma_f16(acc[am][bn], al[am], bh[bn]);
                    }
            }
        }

        // ---- fused epilogue (accumulate into cross-tile registers) ----
        float pm[4], nm[4], cm[8], cnn[8];
        #pragma unroll
        for (int e = 0; e < 4; e++) { pm[e] = 0.f; nm[e] = 3.4e38f; }
        #pragma unroll
        for (int e = 0; e < 8; e++) { cm[e] = 0.f; cnn[e] = 3.4e38f; }

        #pragma unroll
        for (int am = 0; am < 2; am++) {
            #pragma unroll
            for (int h = 0; h < 2; h++) {
                int li = wm * 32 + am * 16 + h * 8 + r_lo;
                int gi = i0 + li;
                int tiv = sti[li];
                #pragma unroll
                for (int bn = 0; bn < 4; bn++) {
                    #pragma unroll
                    for (int e2 = 0; e2 < 2; e2++) {
                        int lj = wn * 32 + bn * 8 + c_lo + e2;
                        int gj = j0 + lj;
                        float s = acc[am][bn][h * 2 + e2];
                        float oms = 1.0f - s;
                        float ee = oms * oms;
                        float d2 = fmaxf(2.0f - 2.0f * s, 0.0f);
                        if (diag && gi > gj) continue;
                        if (diag && gi == gj) {
                            posA += ee;
                            if (tiv == 1) semA += ee;
                            continue;
                        }
                        int tjv = stj[lj];
                        if (tiv == tjv) {
                            posA += 2.0f * ee;
                            qA += ee;
                            if (tiv == 1) semA += 2.0f * ee;
                            pm[am*2 + h] = fmaxf(pm[am*2 + h], d2);
                            cm[bn*2 + e2] = fmaxf(cm[bn*2 + e2], d2);
                        } else {
                            float cc = fmaxf(s - 0.2f, 0.0f);
                            negA += 2.0f * cc * cc;
                            nm[am*2 + h] = fminf(nm[am*2 + h], d2);
                            cnn[bn*2 + e2] = fminf(cnn[bn*2 + e2], d2);
                        }
                    }
                }
            }
        }

        #pragma unroll
        for (int am = 0; am < 2; am++)
            #pragma unroll
            for (int h = 0; h < 2; h++) {
                int li = wm * 32 + am * 16 + h * 8 + r_lo;
                if (pm[am*2+h] > 0.0f)    atomicMax(&srp[li], __float_as_uint(pm[am*2+h]));
                if (nm[am*2+h] < 3.3e38f) atomicMin(&srn[li], __float_as_uint(nm[am*2+h]));
            }
        #pragma unroll
        for (int bn = 0; bn < 4; bn++)
            #pragma unroll
            for (int e2 = 0; e2 < 2; e2++) {
                int lj = wn * 32 + bn * 8 + c_lo + e2;
                if (cm[bn*2+e2] > 0.0f)     atomicMax(&scp[lj], __float_as_uint(cm[bn*2+e2]));
                if (cnn[bn*2+e2] < 3.3e38f) atomicMin(&scn[lj], __float_as_uint(cnn[bn*2+e2]));
            }
        __syncthreads();

        if (tid < 128) {
            if (srp[tid] != 0u)          atomicMax(&g_posd2[i0 + tid], srp[tid]);
            if (srn[tid] != 0x7F7FFFFFu) atomicMin(&g_negd2[i0 + tid], srn[tid]);
            if (scp[tid] != 0u)          atomicMax(&g_posd2[j0 + tid], scp[tid]);
            if (scn[tid] != 0x7F7FFFFFu) atomicMin(&g_negd2[j0 + tid], scn[tid]);
        }
        // top-of-loop __syncthreads separates these global merges from the next reset
    }

    // ---- once per CTA: reduce the four sums ----
    float vals[4] = {posA, negA, semA, qA};
    #pragma unroll
    for (int r = 0; r < 4; r++) {
        sredf[tid] = vals[r];
        __syncthreads();
        for (int s = GT/2; s; s >>= 1) {
            if (tid < s) sredf[tid] += sredf[tid + s];
            __syncthreads();
        }
        if (tid == 0) atomicAdd(&g_acc[r], (double)sredf[0]);
        __syncthreads();
    }

    // ---- last-CTA finalize ----
    __threadfence();
    __shared__ int s_rank;
    if (tid == 0) s_rank = atomicAdd(&g_done, 1);
    __syncthreads();
    if (s_rank != NPERS - 1) return;

    __shared__ double s_sum[5];
    __shared__ int    s_c[CN];
    if (w == 0) {
        double p[5];
        #pragma unroll
        for (int r = 0; r < 5; r++) p[r] = g_rows_part[lane][r];
        int c[CN];
        #pragma unroll
        for (int r = 0; r < CN; r++) c[r] = g_cnt_part[lane][r];
        #pragma unroll
        for (int r = 0; r < 5; r++) {
            double v = p[r];
            for (int o = 16; o; o >>= 1) v += __shfl_xor_sync(0xffffffffu, v, o);
            if (lane == 0) s_sum[r] = v;
        }
        #pragma unroll
        for (int r = 0; r < CN; r++) {
            int v = c[r];
            for (int o = 16; o; o >>= 1) v += __shfl_xor_sync(0xffffffffu, v, o);
            if (lane == 0) s_c[r] = v;
        }
    }
    __syncthreads();
    int c0 = s_c[0], c1 = s_c[1], c2 = s_c[2];

    __shared__ double sdd[GT];
    __shared__ int    sci[GT];
    double tsum = 0.0; int tcnt = 0;
    for (int i = tid; i < BN; i += GT) {
        int t = targets[i];
        int ct = (t == 0) ? c0 : (t == 1) ? c1 : c2;
        if ((ct >= 2) && ((BN - ct) >= 1)) {
            float hp = sqrtf(__uint_as_float(g_posd2[i]));
            float hn = sqrtf(__uint_as_float(g_negd2[i]));
            float margin = 1.5f * ((t == 1) ? 2.5f : 1.0f);
            float tl = fmaxf(hp - hn + margin, 0.0f);
            tsum += (double)tl;
            tcnt++;
        }
    }
    sdd[tid] = tsum; sci[tid] = tcnt;
    __syncthreads();
    for (int s = GT/2; s; s >>= 1) {
        if (tid < s) { sdd[tid] += sdd[tid + s]; sci[tid] += sci[tid + s]; }
        __syncthreads();
    }
    if (tid == 0) {
        double triplet = (sci[0] > 0) ? sdd[0] / (double)(sci[0] > 1 ? sci[0] : 1) : 0.0;
        double focal = s_sum[0] / (double)BN;
        double wsum = (double)c0*cw[0] + (double)c1*cw[1] + (double)c2*cw[2];
        double ce = s_sum[1] / wsum;
        double boundary = s_sum[2] / ((double)BN + 1e-8);
        double contrastive = (g_acc[0] + g_acc[1] + 4.0*g_acc[2]) / ((double)BN*(double)BN + 1e-8);
        long long sp = (long long)c0*c0 + (long long)c1*c1 + (long long)c2*c2;
        long long npairs = (sp - BN) / 2;
        double q = g_acc[3] / (double)(npairs > 1 ? npairs : 1);
        if (c2 > 0) q *= 1.0 + 2.5 * ((double)c2 / (double)BN);
        double quality = (npairs > 0) ? q : 0.0;
        int epoch = epoch_p[0];
        double ann = (double)epoch / 25.0; ann *= ann; if (ann > 1.0) ann = 1.0;
        double evid = s_sum[3] / (double)BN + ann * 0.2 * (s_sum[4] / (double)BN);
        out[0] = (float)(0.4*focal + 0.3*ce + 0.15*boundary
                       + 0.1*contrastive + 0.1*triplet + 0.1*quality + 0.1*evid);
    }
}

// ---------------- launcher ----------------
extern "C" void kernel_launch(void* const* d_in, const int* in_sizes, int n_in,
                              void* d_out, int out_size) {
    const float* logits   = (const float*)d_in[0];
    const int*   targets  = (const int*)d_in[1];
    const float* features = (const float*)d_in[2];
    const float* alpha    = (const float*)d_in[3];
    const int*   epoch    = (const int*)d_in[4];
    const float* fa       = (const float*)d_in[5];
    const float* cw       = (const float*)d_in[6];
    float* out = (float*)d_out;

    cudaFuncSetAttribute(k_gram, cudaFuncAttributeMaxDynamicSharedMemorySize, DSMEM_BYTES);

    k_prep<<<BN + NRB, 128>>>(features, logits, targets, alpha, fa, cw);
    k_gram<<<NPERS, GT, DSMEM_BYTES>>>(targets, cw, epoch, out);
}

// round 9
// speedup vs baseline: 9.0414x; 1.2168x over previous
#include <cuda_runtime.h>
#include <cuda_fp16.h>
#include <math.h>
#include <stdint.h>

#define BN 4096
#define DN 512
#define CN 3
#define NT 32                       // 4096/128 tiles per dim
#define NBLK (NT * (NT + 1) / 2)    // 528 upper-tri tile pairs
#define NCHUNK 8                    // K chunks of 64
#define STAGE_BYTES 32768           // 2 tiles x 16KB (A_hi, B_hi)
#define NSTAGE 4
#define DSMEM_BYTES (NSTAGE * STAGE_BYTES)
#define NRB 32                      // row-scalar blocks (128 thr each)
#define GT 512                      // k_gram threads
#define NPERS 148                   // persistent CTAs

// ---------------- device scratch ----------------
__device__ __align__(16) __half g_hi[BN * DN];
__device__ unsigned int g_posd2[BN];
__device__ unsigned int g_negd2[BN];
__device__ double       g_acc[4];            // 0 pos 1 neg 2 semi 3 q
__device__ double       g_rows_part[NRB][5];
__device__ int          g_cnt_part[NRB][CN];
__device__ int          g_done;
__device__ int          g_work;

// ---------------- PTX helpers (base sm_103-legal only) ----------------
__device__ __forceinline__ uint32_t smem_u32(const void* p) {
    uint32_t a;
    asm("{ .reg .u64 t; cvta.to.shared.u64 t, %1; cvt.u32.u64 %0, t; }" : "=r"(a) : "l"(p));
    return a;
}
#define SW128(x) ((x) ^ (((x) >> 3) & 0x70))

__device__ __forceinline__ void cp16(uint32_t smem, const void* g) {
    asm volatile("cp.async.cg.shared.global [%0], [%1], 16;" :: "r"(smem), "l"(g));
}
#define CP_COMMIT()  asm volatile("cp.async.commit_group;" ::: "memory")
#define CP_WAIT(n)   asm volatile("cp.async.wait_group %0;" :: "n"(n) : "memory")

__device__ __forceinline__ void ldsm_x4(uint32_t& r0, uint32_t& r1, uint32_t& r2, uint32_t& r3,
                                        uint32_t addr) {
    asm volatile("ldmatrix.sync.aligned.m8n8.x4.shared.b16 {%0,%1,%2,%3}, [%4];"
                 : "=r"(r0), "=r"(r1), "=r"(r2), "=r"(r3) : "r"(addr));
}

__device__ __forceinline__ void mma_f16(float* c, const uint32_t* a, const uint32_t* b) {
    asm volatile("mma.sync.aligned.m16n8k16.row.col.f32.f16.f16.f32 "
                 "{%0,%1,%2,%3}, {%4,%5,%6,%7}, {%8,%9}, {%0,%1,%2,%3};"
                 : "+f"(c[0]), "+f"(c[1]), "+f"(c[2]), "+f"(c[3])
                 : "r"(a[0]), "r"(a[1]), "r"(a[2]), "r"(a[3]), "r"(b[0]), "r"(b[1]));
}

// ---------------- misc helpers ----------------
__device__ __forceinline__ float digamma_f(float x) {
    float r = 0.0f;
    while (x < 6.0f) { r -= 1.0f / x; x += 1.0f; }
    float f = 1.0f / (x * x);
    return logf(x) - 0.5f / x
        - f * (1.0f/12.0f - f * (1.0f/120.0f - f * (1.0f/252.0f - f * (1.0f/240.0f))))
        + r;
}

// ---------------- prep kernel ----------------
__global__ void k_prep(const float* __restrict__ f, const float* __restrict__ logits,
                       const int* __restrict__ targets, const float* __restrict__ alpha,
                       const float* __restrict__ fa, const float* __restrict__ cw) {
    int tid = threadIdx.x;
    if (blockIdx.x < BN) {
        int row = blockIdx.x;
        float4 v = ((const float4*)(f + (size_t)row * DN))[tid];
        float ss = v.x*v.x + v.y*v.y + v.z*v.z + v.w*v.w;
        for (int o = 16; o; o >>= 1) ss += __shfl_xor_sync(0xffffffffu, ss, o);
        __shared__ float sred[4];
        if ((tid & 31) == 0) sred[tid >> 5] = ss;
        __syncthreads();
        __shared__ float sinv;
        if (tid == 0) {
            float n = sqrtf(sred[0] + sred[1] + sred[2] + sred[3]);
            sinv = 1.0f / fmaxf(n, 1e-12f);
        }
        __syncthreads();
        float inv = sinv;
        float x0 = v.x*inv, x1 = v.y*inv, x2 = v.z*inv, x3 = v.w*inv;
        __half h0 = __float2half_rn(x0), h1 = __float2half_rn(x1);
        __half h2 = __float2half_rn(x2), h3 = __float2half_rn(x3);
        uint2 hv;
        hv.x = (uint32_t)__half_as_ushort(h0) | ((uint32_t)__half_as_ushort(h1) << 16);
        hv.y = (uint32_t)__half_as_ushort(h2) | ((uint32_t)__half_as_ushort(h3) << 16);
        ((uint2*)g_hi)[(size_t)row * 128 + tid] = hv;

        if (tid == 0) { g_posd2[row] = 0u; g_negd2[row] = 0x7F7FFFFFu; }
        if (row == 0) {
            if (tid < 4) g_acc[tid] = 0.0;
            if (tid == 4) g_done = 0;
            if (tid == 5) g_work = 0;
        }
    } else {
        int rb = blockIdx.x - BN;
        int i = rb * 128 + tid;
        int t = targets[i];

        float l0 = logits[3*i], l1 = logits[3*i+1], l2 = logits[3*i+2];
        float m  = fmaxf(l0, fmaxf(l1, l2));
        float e0 = expf(l0-m), e1 = expf(l1-m), e2 = expf(l2-m);
        float Z  = e0 + e1 + e2;
        float lse = m + logf(Z);
        float lp0 = l0-lse, lp1 = l1-lse, lp2 = l2-lse;
        float lpt = (t == 0) ? lp0 : (t == 1) ? lp1 : lp2;
        float nll = -lpt;
        float ce_ls = 0.9f * nll - 0.1f * ((lp0+lp1+lp2) * (1.0f/3.0f));
        float pt = expf(-ce_ls);
        float om = 1.0f - pt;
        float fterm = fa[t] * om * om * ce_ls;
        float wnll  = cw[t] * nll;
        float p0 = e0/Z, p1 = e1/Z, p2 = e2/Z;
        float bterm = (t == 0) ? (p1 + 0.6f*p2)
                    : (t == 2) ? (p1 + 0.4f*p0)
                    :            4.5f * (1.0f - p1 + 0.3f*(p0 + p2));

        float a0 = alpha[3*i], a1 = alpha[3*i+1], a2 = alpha[3*i+2];
        float S  = a0 + a1 + a2 + 1e-8f;
        float at = (t == 0) ? a0 : (t == 1) ? a1 : a2;
        float lik = digamma_f(S) - digamma_f(at + 1e-8f);
        float b0 = (t == 0) ? 1.0f : a0;
        float b1 = (t == 1) ? 1.0f : a1;
        float b2 = (t == 2) ? 1.0f : a2;
        float ats = b0 + b1 + b2 + 1e-8f;
        float dga = digamma_f(ats + 1e-8f);
        float kl = lgammaf(ats) - (lgammaf(b0+1e-8f) + lgammaf(b1+1e-8f) + lgammaf(b2+1e-8f))
                 + (b0-1.0f) * (digamma_f(b0+1e-8f) - dga)
                 + (b1-1.0f) * (digamma_f(b1+1e-8f) - dga)
                 + (b2-1.0f) * (digamma_f(b2+1e-8f) - dga);

        double vals[5] = { (double)fterm, (double)wnll, (double)bterm, (double)lik, (double)kl };
        __shared__ double swp[4][5];
        int lane = tid & 31, w = tid >> 5;
        #pragma unroll
        for (int r = 0; r < 5; r++) {
            double v = vals[r];
            for (int o = 16; o; o >>= 1) v += __shfl_xor_sync(0xffffffffu, v, o);
            if (lane == 0) swp[w][r] = v;
        }
        __shared__ int sh[CN];
        if (tid < CN) sh[tid] = 0;
        __syncthreads();
        atomicAdd(&sh[t], 1);
        __syncthreads();
        if (tid < 5)  g_rows_part[rb][tid] = swp[0][tid] + swp[1][tid] + swp[2][tid] + swp[3][tid];
        if (tid < CN) g_cnt_part[rb][tid] = sh[tid];
    }
}

// gmem -> smem stage loader (cp.async): A_hi + B_hi — 4 x 16B per thread
__device__ __forceinline__ void load_chunk(uint32_t sb, int i0, int j0, int c, int tid) {
    const uint4* gh4 = (const uint4*)g_hi;
    #pragma unroll
    for (int p = 0; p < 2; p++) {
        int lin = p * GT + tid;
        int r = lin >> 3, q = lin & 7;
        uint32_t so = SW128((uint32_t)(r * 128 + q * 16));
        cp16(sb +         so, gh4 + (size_t)(i0 + r) * 64 + c * 8 + q);
        cp16(sb + 16384 + so, gh4 + (size_t)(j0 + r) * 64 + c * 8 + q);
    }
}

// persistent HMMA Gram kernel + last-CTA finalize
__global__ void __launch_bounds__(GT, 1) k_gram(const int* __restrict__ targets,
                                                const float* __restrict__ cw,
                                                const int* __restrict__ epoch_p,
                                                float* __restrict__ out) {
    extern __shared__ __align__(1024) char dsm_raw[];
    __shared__ int sti[128], stj[128];
    __shared__ unsigned int srp[128], srn[128], scp[128], scn[128];
    __shared__ float sredf[GT];
    __shared__ int s_tile;

    int tid = threadIdx.x;
    int w = tid >> 5, lane = tid & 31;
    int wm = w >> 2, wn = w & 3;     // 4x4 warp grid -> 32x32 region per warp
    uint32_t dsm = smem_u32(dsm_raw);

    int a_row = wm * 32 + (lane & 15);
    int a_colb = (lane >> 4) * 8;
    int b_row = wn * 32 + (lane & 7) + ((lane >> 4) << 3);
    int b_colb = ((lane >> 3) & 1) * 8;
    int r_lo = lane >> 2;
    int c_lo = (lane & 3) * 2;

    // cross-tile accumulators (reduced once at the end)
    float posA = 0.f, negA = 0.f, semA = 0.f, qA = 0.f;

    for (;;) {
        if (tid == 0) s_tile = atomicAdd(&g_work, 1);
        __syncthreads();   // broadcasts s_tile; also separates prior tile's smem use
        int tile = s_tile;
        if (tile >= NBLK) break;

        int bi = 0, rem = tile;
        while (rem >= NT - bi) { rem -= NT - bi; bi++; }
        int bj = bi + rem;
        int i0 = bi * 128, j0 = bj * 128;
        bool diag = (bi == bj);

        if (tid < 128) {
            sti[tid] = targets[i0 + tid];
            stj[tid] = targets[j0 + tid];
            srp[tid] = 0u;            srn[tid] = 0x7F7FFFFFu;
            scp[tid] = 0u;            scn[tid] = 0x7F7FFFFFu;
        }

        float acc[2][4][4];
        #pragma unroll
        for (int am = 0; am < 2; am++)
            #pragma unroll
            for (int bn = 0; bn < 4; bn++)
                #pragma unroll
                for (int e = 0; e < 4; e++) acc[am][bn][e] = 0.0f;

        load_chunk(dsm,                   i0, j0, 0, tid); CP_COMMIT();
        load_chunk(dsm +     STAGE_BYTES, i0, j0, 1, tid); CP_COMMIT();
        load_chunk(dsm + 2 * STAGE_BYTES, i0, j0, 2, tid); CP_COMMIT();

        #pragma unroll
        for (int c = 0; c < NCHUNK; c++) {
            if (c <= NCHUNK - 3)      CP_WAIT(2);
            else if (c == NCHUNK - 2) CP_WAIT(1);
            else                      CP_WAIT(0);
            __syncthreads();   // chunk c resident; stage (c+3)%4 free for reuse
            if (c + 3 < NCHUNK) {
                load_chunk(dsm + ((c + 3) % NSTAGE) * STAGE_BYTES, i0, j0, c + 3, tid);
                CP_COMMIT();
            }
            uint32_t sb = dsm + (c % NSTAGE) * STAGE_BYTES;

            #pragma unroll
            for (int ks = 0; ks < 4; ks++) {
                int k0 = ks * 16;
                uint32_t ah[2][4], bh[4][2];
                #pragma unroll
                for (int am = 0; am < 2; am++) {
                    uint32_t off = SW128((uint32_t)((a_row + am * 16) * 128 + (k0 + a_colb) * 2));
                    ldsm_x4(ah[am][0], ah[am][1], ah[am][2], ah[am][3], sb + off);
                }
                #pragma unroll
                for (int bp = 0; bp < 2; bp++) {
                    uint32_t off = SW128((uint32_t)((b_row + bp * 16) * 128 + (k0 + b_colb) * 2));
                    ldsm_x4(bh[bp*2][0], bh[bp*2][1], bh[bp*2+1][0], bh[bp*2+1][1], sb + 16384 + off);
                }
                #pragma unroll
                for (int am = 0; am < 2; am++)
                    #pragma unroll
                    for (int bn = 0; bn < 4; bn++)
                        mma_f16(acc[am][bn], ah[am], bh[bn]);
            }
        }

        // ---- fused epilogue (accumulate into cross-tile registers) ----
        float pm[4], nm[4], cm[8], cnn[8];
        #pragma unroll
        for (int e = 0; e < 4; e++) { pm[e] = 0.f; nm[e] = 3.4e38f; }
        #pragma unroll
        for (int e = 0; e < 8; e++) { cm[e] = 0.f; cnn[e] = 3.4e38f; }

        #pragma unroll
        for (int am = 0; am < 2; am++) {
            #pragma unroll
            for (int h = 0; h < 2; h++) {
                int li = wm * 32 + am * 16 + h * 8 + r_lo;
                int gi = i0 + li;
                int tiv = sti[li];
                #pragma unroll
                for (int bn = 0; bn < 4; bn++) {
                    #pragma unroll
                    for (int e2 = 0; e2 < 2; e2++) {
                        int lj = wn * 32 + bn * 8 + c_lo + e2;
                        int gj = j0 + lj;
                        float s = acc[am][bn][h * 2 + e2];
                        float oms = 1.0f - s;
                        float ee = oms * oms;
                        float d2 = fmaxf(2.0f - 2.0f * s, 0.0f);
                        if (diag && gi > gj) continue;
                        if (diag && gi == gj) {
                            posA += ee;
                            if (tiv == 1) semA += ee;
                            continue;
                        }
                        int tjv = stj[lj];
                        if (tiv == tjv) {
                            posA += 2.0f * ee;
                            qA += ee;
                            if (tiv == 1) semA += 2.0f * ee;
                            pm[am*2 + h] = fmaxf(pm[am*2 + h], d2);
                            cm[bn*2 + e2] = fmaxf(cm[bn*2 + e2], d2);
                        } else {
                            float cc = fmaxf(s - 0.2f, 0.0f);
                            negA += 2.0f * cc * cc;
                            nm[am*2 + h] = fminf(nm[am*2 + h], d2);
                            cnn[bn*2 + e2] = fminf(cnn[bn*2 + e2], d2);
                        }
                    }
                }
            }
        }

        #pragma unroll
        for (int am = 0; am < 2; am++)
            #pragma unroll
            for (int h = 0; h < 2; h++) {
                int li = wm * 32 + am * 16 + h * 8 + r_lo;
                if (pm[am*2+h] > 0.0f)    atomicMax(&srp[li], __float_as_uint(pm[am*2+h]));
                if (nm[am*2+h] < 3.3e38f) atomicMin(&srn[li], __float_as_uint(nm[am*2+h]));
            }
        #pragma unroll
        for (int bn = 0; bn < 4; bn++)
            #pragma unroll
            for (int e2 = 0; e2 < 2; e2++) {
                int lj = wn * 32 + bn * 8 + c_lo + e2;
                if (cm[bn*2+e2] > 0.0f)     atomicMax(&scp[lj], __float_as_uint(cm[bn*2+e2]));
                if (cnn[bn*2+e2] < 3.3e38f) atomicMin(&scn[lj], __float_as_uint(cnn[bn*2+e2]));
            }
        __syncthreads();

        if (tid < 128) {
            if (srp[tid] != 0u)          atomicMax(&g_posd2[i0 + tid], srp[tid]);
            if (srn[tid] != 0x7F7FFFFFu) atomicMin(&g_negd2[i0 + tid], srn[tid]);
            if (scp[tid] != 0u)          atomicMax(&g_posd2[j0 + tid], scp[tid]);
            if (scn[tid] != 0x7F7FFFFFu) atomicMin(&g_negd2[j0 + tid], scn[tid]);
        }
        // top-of-loop __syncthreads separates these global merges from the next reset
    }

    // ---- once per CTA: reduce the four sums ----
    float vals[4] = {posA, negA, semA, qA};
    #pragma unroll
    for (int r = 0; r < 4; r++) {
        sredf[tid] = vals[r];
        __syncthreads();
        for (int s = GT/2; s; s >>= 1) {
            if (tid < s) sredf[tid] += sredf[tid + s];
            __syncthreads();
        }
        if (tid == 0) atomicAdd(&g_acc[r], (double)sredf[0]);
        __syncthreads();
    }

    // ---- last-CTA finalize ----
    __threadfence();
    __shared__ int s_rank;
    if (tid == 0) s_rank = atomicAdd(&g_done, 1);
    __syncthreads();
    if (s_rank != NPERS - 1) return;

    __shared__ double s_sum[5];
    __shared__ int    s_c[CN];
    if (w == 0) {
        double p[5];
        #pragma unroll
        for (int r = 0; r < 5; r++) p[r] = g_rows_part[lane][r];
        int c[CN];
        #pragma unroll
        for (int r = 0; r < CN; r++) c[r] = g_cnt_part[lane][r];
        #pragma unroll
        for (int r = 0; r < 5; r++) {
            double v = p[r];
            for (int o = 16; o; o >>= 1) v += __shfl_xor_sync(0xffffffffu, v, o);
            if (lane == 0) s_sum[r] = v;
        }
        #pragma unroll
        for (int r = 0; r < CN; r++) {
            int v = c[r];
            for (int o = 16; o; o >>= 1) v += __shfl_xor_sync(0xffffffffu, v, o);
            if (lane == 0) s_c[r] = v;
        }
    }
    __syncthreads();
    int c0 = s_c[0], c1 = s_c[1], c2 = s_c[2];

    __shared__ double sdd[GT];
    __shared__ int    sci[GT];
    double tsum = 0.0; int tcnt = 0;
    for (int i = tid; i < BN; i += GT) {
        int t = targets[i];
        int ct = (t == 0) ? c0 : (t == 1) ? c1 : c2;
        if ((ct >= 2) && ((BN - ct) >= 1)) {
            float hp = sqrtf(__uint_as_float(g_posd2[i]));
            float hn = sqrtf(__uint_as_float(g_negd2[i]));
            float margin = 1.5f * ((t == 1) ? 2.5f : 1.0f);
            float tl = fmaxf(hp - hn + margin, 0.0f);
            tsum += (double)tl;
            tcnt++;
        }
    }
    sdd[tid] = tsum; sci[tid] = tcnt;
    __syncthreads();
    for (int s = GT/2; s; s >>= 1) {
        if (tid < s) { sdd[tid] += sdd[tid + s]; sci[tid] += sci[tid + s]; }
        __syncthreads();
    }
    if (tid == 0) {
        double triplet = (sci[0] > 0) ? sdd[0] / (double)(sci[0] > 1 ? sci[0] : 1) : 0.0;
        double focal = s_sum[0] / (double)BN;
        double wsum = (double)c0*cw[0] + (double)c1*cw[1] + (double)c2*cw[2];
        double ce = s_sum[1] / wsum;
        double boundary = s_sum[2] / ((double)BN + 1e-8);
        double contrastive = (g_acc[0] + g_acc[1] + 4.0*g_acc[2]) / ((double)BN*(double)BN + 1e-8);
        long long sp = (long long)c0*c0 + (long long)c1*c1 + (long long)c2*c2;
        long long npairs = (sp - BN) / 2;
        double q = g_acc[3] / (double)(npairs > 1 ? npairs : 1);
        if (c2 > 0) q *= 1.0 + 2.5 * ((double)c2 / (double)BN);
        double quality = (npairs > 0) ? q : 0.0;
        int epoch = epoch_p[0];
        double ann = (double)epoch / 25.0; ann *= ann; if (ann > 1.0) ann = 1.0;
        double evid = s_sum[3] / (double)BN + ann * 0.2 * (s_sum[4] / (double)BN);
        out[0] = (float)(0.4*focal + 0.3*ce + 0.15*boundary
                       + 0.1*contrastive + 0.1*triplet + 0.1*quality + 0.1*evid);
    }
}

// ---------------- launcher ----------------
extern "C" void kernel_launch(void* const* d_in, const int* in_sizes, int n_in,
                              void* d_out, int out_size) {
    const float* logits   = (const float*)d_in[0];
    const int*   targets  = (const int*)d_in[1];
    const float* features = (const float*)d_in[2];
    const float* alpha    = (const float*)d_in[3];
    const int*   epoch    = (const int*)d_in[4];
    const float* fa       = (const float*)d_in[5];
    const float* cw       = (const float*)d_in[6];
    float* out = (float*)d_out;

    cudaFuncSetAttribute(k_gram, cudaFuncAttributeMaxDynamicSharedMemorySize, DSMEM_BYTES);

    k_prep<<<BN + NRB, 128>>>(features, logits, targets, alpha, fa, cw);
    k_gram<<<NPERS, GT, DSMEM_BYTES>>>(targets, cw, epoch, out);
}

// round 11
// speedup vs baseline: 9.2979x; 1.0284x over previous
#include <cuda_runtime.h>
#include <cuda_fp16.h>
#include <math.h>
#include <stdint.h>

#define BN 4096
#define DN 512
#define CN 3
#define NT 32                       // 4096/128 tiles per dim
#define NBLK (NT * (NT + 1) / 2)    // 528 upper-tri tile pairs
#define NCHUNK 8                    // K chunks of 64
#define STAGE_BYTES 32768           // 2 tiles x 16KB (A_hi, B_hi)
#define NSTAGE 6
#define DSMEM_BYTES (NSTAGE * STAGE_BYTES)
#define NRW 128                     // row-scalar warps (32 rows each)
#define GT 512                      // k_gram threads
#define NPERS 148                   // persistent CTAs

// ---------------- device scratch ----------------
__device__ __align__(16) __half g_hi[BN * DN];
__device__ unsigned int g_posd2[BN];
__device__ unsigned int g_negd2[BN];
__device__ double       g_acc[4];            // 0 pos 1 neg 2 semi 3 q
__device__ double       g_rows_part[NRW][5];
__device__ int          g_cnt_part[NRW][CN];
__device__ int          g_done;
__device__ int          g_work;

// ---------------- PTX helpers (base sm_103-legal only) ----------------
__device__ __forceinline__ uint32_t smem_u32(const void* p) {
    uint32_t a;
    asm("{ .reg .u64 t; cvta.to.shared.u64 t, %1; cvt.u32.u64 %0, t; }" : "=r"(a) : "l"(p));
    return a;
}
#define SW128(x) ((x) ^ (((x) >> 3) & 0x70))

__device__ __forceinline__ void cp16(uint32_t smem, const void* g) {
    asm volatile("cp.async.cg.shared.global [%0], [%1], 16;" :: "r"(smem), "l"(g));
}
#define CP_COMMIT()  asm volatile("cp.async.commit_group;" ::: "memory")
#define CP_WAIT(n)   asm volatile("cp.async.wait_group %0;" :: "n"(n) : "memory")

__device__ __forceinline__ void ldsm_x4(uint32_t& r0, uint32_t& r1, uint32_t& r2, uint32_t& r3,
                                        uint32_t addr) {
    asm volatile("ldmatrix.sync.aligned.m8n8.x4.shared.b16 {%0,%1,%2,%3}, [%4];"
                 : "=r"(r0), "=r"(r1), "=r"(r2), "=r"(r3) : "r"(addr));
}

__device__ __forceinline__ void mma_f16(float* c, const uint32_t* a, const uint32_t* b) {
    asm volatile("mma.sync.aligned.m16n8k16.row.col.f32.f16.f16.f32 "
                 "{%0,%1,%2,%3}, {%4,%5,%6,%7}, {%8,%9}, {%0,%1,%2,%3};"
                 : "+f"(c[0]), "+f"(c[1]), "+f"(c[2]), "+f"(c[3])
                 : "r"(a[0]), "r"(a[1]), "r"(a[2]), "r"(a[3]), "r"(b[0]), "r"(b[1]));
}

// ---------------- misc helpers ----------------
__device__ __forceinline__ float digamma_f(float x) {
    float r = 0.0f;
    while (x < 6.0f) { r -= 1.0f / x; x += 1.0f; }
    float f = 1.0f / (x * x);
    return logf(x) - 0.5f / x
        - f * (1.0f/12.0f - f * (1.0f/120.0f - f * (1.0f/252.0f - f * (1.0f/240.0f))))
        + r;
}

__device__ __forceinline__ void decode_tile(int t, int& bi, int& bj) {
    float ff = (65.0f - sqrtf(4225.0f - 8.0f * (float)t)) * 0.5f;
    int b = (int)ff;
    if (b < 0) b = 0;
    while (b * NT - (b * (b - 1)) / 2 > t) b--;
    while ((b + 1) * NT - ((b + 1) * b) / 2 <= t) b++;
    bi = b;
    bj = b + (t - (b * NT - (b * (b - 1)) / 2));
}

// ---------------- prep kernel: 148 x 512, warp-per-row norm + warp scalars ----------------
__global__ void __launch_bounds__(GT) k_prep(const float* __restrict__ f, const float* __restrict__ logits,
                       const int* __restrict__ targets, const float* __restrict__ alpha,
                       const float* __restrict__ fa, const float* __restrict__ cw) {
    int tid = threadIdx.x;
    int gid = blockIdx.x * GT + tid;
    int lane = tid & 31;
    int gw = gid >> 5;
    const int TW = NPERS * GT / 32;   // total warps

    // ---- normalization: one warp per row ----
    for (int row = gw; row < BN; row += TW) {
        const float4* fr = (const float4*)(f + (size_t)row * DN);
        float4 v[4];
        float ss = 0.0f;
        #pragma unroll
        for (int i = 0; i < 4; i++) {
            v[i] = fr[lane + 32 * i];
            ss += v[i].x*v[i].x + v[i].y*v[i].y + v[i].z*v[i].z + v[i].w*v[i].w;
        }
        for (int o = 16; o; o >>= 1) ss += __shfl_xor_sync(0xffffffffu, ss, o);
        float inv = 1.0f / fmaxf(sqrtf(ss), 1e-12f);
        uint2* out = (uint2*)g_hi + (size_t)row * 128;
        #pragma unroll
        for (int i = 0; i < 4; i++) {
            __half h0 = __float2half_rn(v[i].x * inv), h1 = __float2half_rn(v[i].y * inv);
            __half h2 = __float2half_rn(v[i].z * inv), h3 = __float2half_rn(v[i].w * inv);
            uint2 hv;
            hv.x = (uint32_t)__half_as_ushort(h0) | ((uint32_t)__half_as_ushort(h1) << 16);
            hv.y = (uint32_t)__half_as_ushort(h2) | ((uint32_t)__half_as_ushort(h3) << 16);
            out[lane + 32 * i] = hv;
        }
    }

    // ---- scalar init ----
    if (gid < BN) { g_posd2[gid] = 0u; g_negd2[gid] = 0x7F7FFFFFu; }
    if (gid < 4) g_acc[gid] = 0.0;
    if (gid == 4) g_done = 0;
    if (gid == 5) g_work = 0;

    // ---- row-scalar terms: warps 0..127, 32 rows each ----
    if (gw < NRW) {
        int i = gw * 32 + lane;
        int t = targets[i];

        float l0 = logits[3*i], l1 = logits[3*i+1], l2 = logits[3*i+2];
        float m  = fmaxf(l0, fmaxf(l1, l2));
        float e0 = expf(l0-m), e1 = expf(l1-m), e2 = expf(l2-m);
        float Z  = e0 + e1 + e2;
        float lse = m + logf(Z);
        float lp0 = l0-lse, lp1 = l1-lse, lp2 = l2-lse;
        float lpt = (t == 0) ? lp0 : (t == 1) ? lp1 : lp2;
        float nll = -lpt;
        float ce_ls = 0.9f * nll - 0.1f * ((lp0+lp1+lp2) * (1.0f/3.0f));
        float pt = expf(-ce_ls);
        float om = 1.0f - pt;
        float fterm = fa[t] * om * om * ce_ls;
        float wnll  = cw[t] * nll;
        float p0 = e0/Z, p1 = e1/Z, p2 = e2/Z;
        float bterm = (t == 0) ? (p1 + 0.6f*p2)
                    : (t == 2) ? (p1 + 0.4f*p0)
                    :            4.5f * (1.0f - p1 + 0.3f*(p0 + p2));

        float a0 = alpha[3*i], a1 = alpha[3*i+1], a2 = alpha[3*i+2];
        float S  = a0 + a1 + a2 + 1e-8f;
        float at = (t == 0) ? a0 : (t == 1) ? a1 : a2;
        float lik = digamma_f(S) - digamma_f(at + 1e-8f);
        float b0 = (t == 0) ? 1.0f : a0;
        float b1 = (t == 1) ? 1.0f : a1;
        float b2 = (t == 2) ? 1.0f : a2;
        float ats = b0 + b1 + b2 + 1e-8f;
        float dga = digamma_f(ats + 1e-8f);
        float kl = lgammaf(ats) - (lgammaf(b0+1e-8f) + lgammaf(b1+1e-8f) + lgammaf(b2+1e-8f))
                 + (b0-1.0f) * (digamma_f(b0+1e-8f) - dga)
                 + (b1-1.0f) * (digamma_f(b1+1e-8f) - dga)
                 + (b2-1.0f) * (digamma_f(b2+1e-8f) - dga);

        double vals[5] = { (double)fterm, (double)wnll, (double)bterm, (double)lik, (double)kl };
        #pragma unroll
        for (int r = 0; r < 5; r++) {
            double v = vals[r];
            for (int o = 16; o; o >>= 1) v += __shfl_xor_sync(0xffffffffu, v, o);
            if (lane == 0) g_rows_part[gw][r] = v;
        }
        #pragma unroll
        for (int r = 0; r < CN; r++) {
            int v = (t == r) ? 1 : 0;
            for (int o = 16; o; o >>= 1) v += __shfl_xor_sync(0xffffffffu, v, o);
            if (lane == 0) g_cnt_part[gw][r] = v;
        }
    }
}

// gmem -> smem stage loader (cp.async): A_hi + B_hi — 4 x 16B per thread
__device__ __forceinline__ void load_chunk(uint32_t sb, int i0, int j0, int c, int tid) {
    const uint4* gh4 = (const uint4*)g_hi;
    #pragma unroll
    for (int p = 0; p < 2; p++) {
        int lin = p * GT + tid;
        int r = lin >> 3, q = lin & 7;
        uint32_t so = SW128((uint32_t)(r * 128 + q * 16));
        cp16(sb +         so, gh4 + (size_t)(i0 + r) * 64 + c * 8 + q);
        cp16(sb + 16384 + so, gh4 + (size_t)(j0 + r) * 64 + c * 8 + q);
    }
}

// persistent HMMA Gram kernel, rolling 6-stage pipeline, + last-CTA finalize
__global__ void __launch_bounds__(GT, 1) k_gram(const int* __restrict__ targets,
                                                const float* __restrict__ cw,
                                                const int* __restrict__ epoch_p,
                                                float* __restrict__ out) {
    extern __shared__ __align__(1024) char dsm_raw[];
    __shared__ int sti[2][128], stj[2][128];
    __shared__ unsigned int srp[2][128], srn[2][128], scp[2][128], scn[2][128];
    __shared__ float sredf[GT];
    __shared__ int s_cur, s_next;

    int tid = threadIdx.x;
    int w = tid >> 5, lane = tid & 31;
    int wm = w >> 2, wn = w & 3;     // 4x4 warp grid -> 32x32 region per warp
    uint32_t dsm = smem_u32(dsm_raw);

    int a_row = wm * 32 + (lane & 15);
    int a_colb = (lane >> 4) * 8;
    int b_row = wn * 32 + (lane & 7) + ((lane >> 4) << 3);
    int b_colb = ((lane >> 3) & 1) * 8;
    int r_lo = lane >> 2;
    int c_lo = (lane & 3) * 2;

    float posA = 0.f, negA = 0.f, semA = 0.f, qA = 0.f;

    if (tid == 0) s_cur = atomicAdd(&g_work, 1);
    __syncthreads();
    int tile = s_cur;                 // < NPERS <= NBLK, always valid
    int bi, bj;
    decode_tile(tile, bi, bj);
    int i0 = bi * 128, j0 = bj * 128;
    int p = 0;
    if (tid < 128) {
        sti[0][tid] = targets[i0 + tid];
        stj[0][tid] = targets[j0 + tid];
        srp[0][tid] = 0u; srn[0][tid] = 0x7F7FFFFFu;
        scp[0][tid] = 0u; scn[0][tid] = 0x7F7FFFFFu;
    }
    int sb0 = 0;   // stage of this tile's chunk 0
    #pragma unroll
    for (int c = 0; c < 6; c++) {
        load_chunk(dsm + (uint32_t)((sb0 + c) % NSTAGE) * STAGE_BYTES, i0, j0, c, tid);
        CP_COMMIT();
    }

    for (;;) {
        bool diag = (bi == bj);
        int i0n = 0, j0n = 0, nt = NBLK;

        float acc[2][4][4];
        #pragma unroll
        for (int am = 0; am < 2; am++)
            #pragma unroll
            for (int bn = 0; bn < 4; bn++)
                #pragma unroll
                for (int e = 0; e < 4; e++) acc[am][bn][e] = 0.0f;

        #pragma unroll
        for (int iter = 0; iter < 4; iter++) {
            CP_WAIT(4);
            __syncthreads();
            if (iter == 0 && tid == 0) s_next = atomicAdd(&g_work, 1);
            if (iter == 1) {
                nt = s_next;   // visible via this iter's __syncthreads
                if (nt < NBLK) {
                    int bin, bjn;
                    decode_tile(nt, bin, bjn);
                    i0n = bin * 128; j0n = bjn * 128;
                }
                if (tid < 128) {
                    if (nt < NBLK) {
                        sti[p ^ 1][tid] = targets[i0n + tid];
                        stj[p ^ 1][tid] = targets[j0n + tid];
                    }
                    srp[p ^ 1][tid] = 0u; srn[p ^ 1][tid] = 0x7F7FFFFFu;
                    scp[p ^ 1][tid] = 0u; scn[p ^ 1][tid] = 0x7F7FFFFFu;
                }
            }

            // compute chunks 2*iter, 2*iter+1
            #pragma unroll
            for (int s2 = 0; s2 < 2; s2++) {
                uint32_t sb = dsm + (uint32_t)((sb0 + 2 * iter + s2) % NSTAGE) * STAGE_BYTES;
                #pragma unroll
                for (int ks = 0; ks < 4; ks++) {
                    int k0 = ks * 16;
                    uint32_t ah[2][4], bh[4][2];
                    #pragma unroll
                    for (int am = 0; am < 2; am++) {
                        uint32_t off = SW128((uint32_t)((a_row + am * 16) * 128 + (k0 + a_colb) * 2));
                        ldsm_x4(ah[am][0], ah[am][1], ah[am][2], ah[am][3], sb + off);
                    }
                    #pragma unroll
                    for (int bp = 0; bp < 2; bp++) {
                        uint32_t off = SW128((uint32_t)((b_row + bp * 16) * 128 + (k0 + b_colb) * 2));
                        ldsm_x4(bh[bp*2][0], bh[bp*2][1], bh[bp*2+1][0], bh[bp*2+1][1], sb + 16384 + off);
                    }
                    #pragma unroll
                    for (int am = 0; am < 2; am++)
                        #pragma unroll
                        for (int bn = 0; bn < 4; bn++)
                            mma_f16(acc[am][bn], ah[am], bh[bn]);
                }
            }

            // issue loads for chunk slots 2*iter+6, 2*iter+7 into the stages just freed
            #pragma unroll
            for (int s2 = 0; s2 < 2; s2++) {
                int cl = 2 * iter + 6 + s2;
                uint32_t stg = dsm + (uint32_t)((sb0 + cl) % NSTAGE) * STAGE_BYTES;
                if (cl < NCHUNK) load_chunk(stg, i0, j0, cl, tid);
                else if (iter >= 1 && nt < NBLK) load_chunk(stg, i0n, j0n, cl - NCHUNK, tid);
                CP_COMMIT();
            }
        }

        // ---- fused epilogue (accumulate into cross-tile registers) ----
        float pm[4], nm[4], cm[8], cnn[8];
        #pragma unroll
        for (int e = 0; e < 4; e++) { pm[e] = 0.f; nm[e] = 3.4e38f; }
        #pragma unroll
        for (int e = 0; e < 8; e++) { cm[e] = 0.f; cnn[e] = 3.4e38f; }

        #pragma unroll
        for (int am = 0; am < 2; am++) {
            #pragma unroll
            for (int h = 0; h < 2; h++) {
                int li = wm * 32 + am * 16 + h * 8 + r_lo;
                int gi = i0 + li;
                int tiv = sti[p][li];
                #pragma unroll
                for (int bn = 0; bn < 4; bn++) {
                    #pragma unroll
                    for (int e2 = 0; e2 < 2; e2++) {
                        int lj = wn * 32 + bn * 8 + c_lo + e2;
                        int gj = j0 + lj;
                        float s = acc[am][bn][h * 2 + e2];
                        float oms = 1.0f - s;
                        float ee = oms * oms;
                        float d2 = fmaxf(2.0f - 2.0f * s, 0.0f);
                        if (diag && gi > gj) continue;
                        if (diag && gi == gj) {
                            posA += ee;
                            if (tiv == 1) semA += ee;
                            continue;
                        }
                        int tjv = stj[p][lj];
                        if (tiv == tjv) {
                            posA += 2.0f * ee;
                            qA += ee;
                            if (tiv == 1) semA += 2.0f * ee;
                            pm[am*2 + h] = fmaxf(pm[am*2 + h], d2);
                            cm[bn*2 + e2] = fmaxf(cm[bn*2 + e2], d2);
                        } else {
                            float cc = fmaxf(s - 0.2f, 0.0f);
                            negA += 2.0f * cc * cc;
                            nm[am*2 + h] = fminf(nm[am*2 + h], d2);
                            cnn[bn*2 + e2] = fminf(cnn[bn*2 + e2], d2);
                        }
                    }
                }
            }
        }

        #pragma unroll
        for (int am = 0; am < 2; am++)
            #pragma unroll
            for (int h = 0; h < 2; h++) {
                int li = wm * 32 + am * 16 + h * 8 + r_lo;
                if (pm[am*2+h] > 0.0f)    atomicMax(&srp[p][li], __float_as_uint(pm[am*2+h]));
                if (nm[am*2+h] < 3.3e38f) atomicMin(&srn[p][li], __float_as_uint(nm[am*2+h]));
            }
        #pragma unroll
        for (int bn = 0; bn < 4; bn++)
            #pragma unroll
            for (int e2 = 0; e2 < 2; e2++) {
                int lj = wn * 32 + bn * 8 + c_lo + e2;
                if (cm[bn*2+e2] > 0.0f)     atomicMax(&scp[p][lj], __float_as_uint(cm[bn*2+e2]));
                if (cnn[bn*2+e2] < 3.3e38f) atomicMin(&scn[p][lj], __float_as_uint(cnn[bn*2+e2]));
            }
        __syncthreads();

        if (tid < 128) {
            if (srp[p][tid] != 0u)          atomicMax(&g_posd2[i0 + tid], srp[p][tid]);
            if (srn[p][tid] != 0x7F7FFFFFu) atomicMin(&g_negd2[i0 + tid], srn[p][tid]);
            if (scp[p][tid] != 0u)          atomicMax(&g_posd2[j0 + tid], scp[p][tid]);
            if (scn[p][tid] != 0x7F7FFFFFu) atomicMin(&g_negd2[j0 + tid], scn[p][tid]);
        }

        if (nt >= NBLK) break;
        tile = nt;
        decode_tile(tile, bi, bj);
        i0 = bi * 128; j0 = bj * 128;
        p ^= 1;
        sb0 = (sb0 + 2) % NSTAGE;   // (sb0 + 8) % 6
    }
    CP_WAIT(0);

    // ---- once per CTA: reduce the four sums ----
    float vals[4] = {posA, negA, semA, qA};
    #pragma unroll
    for (int r = 0; r < 4; r++) {
        sredf[tid] = vals[r];
        __syncthreads();
        for (int s = GT/2; s; s >>= 1) {
            if (tid < s) sredf[tid] += sredf[tid + s];
            __syncthreads();
        }
        if (tid == 0) atomicAdd(&g_acc[r], (double)sredf[0]);
        __syncthreads();
    }

    // ---- last-CTA finalize ----
    __threadfence();
    __shared__ int s_rank;
    if (tid == 0) s_rank = atomicAdd(&g_done, 1);
    __syncthreads();
    if (s_rank != NPERS - 1) return;

    __shared__ double s_sum[5];
    __shared__ int    s_c[CN];
    if (w == 0) {
        double p5[5] = {0,0,0,0,0};
        int    c3[CN] = {0,0,0};
        #pragma unroll
        for (int q = 0; q < 4; q++) {
            int idx = lane + 32 * q;
            #pragma unroll
            for (int r = 0; r < 5; r++) p5[r] += g_rows_part[idx][r];
            #pragma unroll
            for (int r = 0; r < CN; r++) c3[r] += g_cnt_part[idx][r];
        }
        #pragma unroll
        for (int r = 0; r < 5; r++) {
            double v = p5[r];
            for (int o = 16; o; o >>= 1) v += __shfl_xor_sync(0xffffffffu, v, o);
            if (lane == 0) s_sum[r] = v;
        }
        #pragma unroll
        for (int r = 0; r < CN; r++) {
            int v = c3[r];
            for (int o = 16; o; o >>= 1) v += __shfl_xor_sync(0xffffffffu, v, o);
            if (lane == 0) s_c[r] = v;
        }
    }
    __syncthreads();
    int c0 = s_c[0], c1 = s_c[1], c2 = s_c[2];

    __shared__ double sdd[GT];
    __shared__ int    sci[GT];
    double tsum = 0.0; int tcnt = 0;
    for (int i = tid; i < BN; i += GT) {
        int t = targets[i];
        int ct = (t == 0) ? c0 : (t == 1) ? c1 : c2;
        if ((ct >= 2) && ((BN - ct) >= 1)) {
            float hp = sqrtf(__uint_as_float(g_posd2[i]));
            float hn = sqrtf(__uint_as_float(g_negd2[i]));
            float margin = 1.5f * ((t == 1) ? 2.5f : 1.0f);
            float tl = fmaxf(hp - hn + margin, 0.0f);
            tsum += (double)tl;
            tcnt++;
        }
    }
    sdd[tid] = tsum; sci[tid] = tcnt;
    __syncthreads();
    for (int s = GT/2; s; s >>= 1) {
        if (tid < s) { sdd[tid] += sdd[tid + s]; sci[tid] += sci[tid + s]; }
        __syncthreads();
    }
    if (tid == 0) {
        double triplet = (sci[0] > 0) ? sdd[0] / (double)(sci[0] > 1 ? sci[0] : 1) : 0.0;
        double focal = s_sum[0] / (double)BN;
        double wsum = (double)c0*cw[0] + (double)c1*cw[1] + (double)c2*cw[2];
        double ce = s_sum[1] / wsum;
        double boundary = s_sum[2] / ((double)BN + 1e-8);
        double contrastive = (g_acc[0] + g_acc[1] + 4.0*g_acc[2]) / ((double)BN*(double)BN + 1e-8);
        long long sp = (long long)c0*c0 + (long long)c1*c1 + (long long)c2*c2;
        long long npairs = (sp - BN) / 2;
        double q = g_acc[3] / (double)(npairs > 1 ? npairs : 1);
        if (c2 > 0) q *= 1.0 + 2.5 * ((double)c2 / (double)BN);
        double quality = (npairs > 0) ? q : 0.0;
        int epoch = epoch_p[0];
        double ann = (double)epoch / 25.0; ann *= ann; if (ann > 1.0) ann = 1.0;
        double evid = s_sum[3] / (double)BN + ann * 0.2 * (s_sum[4] / (double)BN);
        out[0] = (float)(0.4*focal + 0.3*ce + 0.15*boundary
                       + 0.1*contrastive + 0.1*triplet + 0.1*quality + 0.1*evid);
    }
}

// ---------------- launcher ----------------
extern "C" void kernel_launch(void* const* d_in, const int* in_sizes, int n_in,
                              void* d_out, int out_size) {
    const float* logits   = (const float*)d_in[0];
    const int*   targets  = (const int*)d_in[1];
    const float* features = (const float*)d_in[2];
    const float* alpha    = (const float*)d_in[3];
    const int*   epoch    = (const int*)d_in[4];
    const float* fa       = (const float*)d_in[5];
    const float* cw       = (const float*)d_in[6];
    float* out = (float*)d_out;

    cudaFuncSetAttribute(k_gram, cudaFuncAttributeMaxDynamicSharedMemorySize, DSMEM_BYTES);

    k_prep<<<NPERS, GT>>>(features, logits, targets, alpha, fa, cw);
    k_gram<<<NPERS, GT, DSMEM_BYTES>>>(targets, cw, epoch, out);
}